// round 12
// baseline (speedup 1.0000x reference)
#include <cuda_runtime.h>
#include <cuda_fp16.h>
#include <cstdint>

#define D 128
#define NMAX 50176
#define EMAX 1048576

typedef unsigned long long ull;

// ---------------- scratch ----------------
static __device__ float g_h[NMAX * D];
static __device__ __align__(16) __half g_xf[NMAX * D];   // dinv_in*relu(xf), fp16
static __device__ __align__(16) __half g_xr[NMAX * D];   // dinv_out*relu(xr), fp16
static __device__ float g_aggf[NMAX * D];
static __device__ float g_aggr[NMAX * D];
static __device__ float g_deg_in[NMAX];
static __device__ float g_deg_out[NMAX];
static __device__ float g_dinv_in[NMAX];
static __device__ float g_dinv_out[NMAX];
static __device__ float g_rdeg_in[NMAX];
static __device__ float g_rdeg_out[NMAX];
static __device__ int g_off_in[NMAX + 1];
static __device__ int g_off_out[NMAX + 1];
static __device__ int g_fill_in[NMAX];
static __device__ int g_fill_out[NMAX];
static __device__ int g_csr_in[EMAX];
static __device__ int g_csr_out[EMAX];

__device__ __forceinline__ float lrelu(float v) { return v >= 0.f ? v : 0.1f * v; }
__device__ __forceinline__ float4 lrelu4(float4 v) {
    return make_float4(lrelu(v.x), lrelu(v.y), lrelu(v.z), lrelu(v.w));
}
__device__ __forceinline__ void fma2(ull& d, ull a, ull b) {
    asm("fma.rn.f32x2 %0, %1, %2, %0;" : "+l"(d) : "l"(a), "l"(b));
}
__device__ __forceinline__ float unpack_sum(ull v) {
    float2 p = *(float2*)&v;
    return p.x + p.y;
}

// ---------------- mma.sync helpers (baseline sm_80+, OK on plain sm_100) ----------------
__device__ __forceinline__ uint32_t smem_u32(const void* p) {
    uint32_t a;
    asm("{ .reg .u64 t; cvta.to.shared.u64 t, %1; cvt.u32.u64 %0, t; }" : "=r"(a) : "l"(p));
    return a;
}
__device__ __forceinline__ void ldsm4(uint32_t* r, uint32_t addr) {
    asm volatile("ldmatrix.sync.aligned.m8n8.x4.shared.b16 {%0,%1,%2,%3}, [%4];"
                 : "=r"(r[0]), "=r"(r[1]), "=r"(r[2]), "=r"(r[3]) : "r"(addr));
}
__device__ __forceinline__ void mma16816(float* c, const uint32_t* a, uint32_t b0, uint32_t b1) {
    asm volatile("mma.sync.aligned.m16n8k16.row.col.f32.f16.f16.f32 "
                 "{%0,%1,%2,%3}, {%4,%5,%6,%7}, {%8,%9}, {%0,%1,%2,%3};"
                 : "+f"(c[0]), "+f"(c[1]), "+f"(c[2]), "+f"(c[3])
                 : "r"(a[0]), "r"(a[1]), "r"(a[2]), "r"(a[3]), "r"(b0), "r"(b1));
}

#define NETB 16   // blocks for net-encoder path; rest do instance path

// ---------------- fused encoders (+ degree init) ----------------
__global__ void __launch_bounds__(512, 1)
enc_kernel(const float* __restrict__ x, const float* __restrict__ xn,
           const float* __restrict__ W1, const float* __restrict__ b1,
           const float* __restrict__ W2, const float* __restrict__ b2,
           const float* __restrict__ nW1, const float* __restrict__ nb1,
           const float* __restrict__ nW2, const float* __restrict__ nb2,
           int NI, int NN, int N, float* __restrict__ out)
{
    for (int i = blockIdx.x * 512 + threadIdx.x; i < N; i += gridDim.x * 512) {
        g_deg_in[i] = 1.0f; g_deg_out[i] = 1.0f;
    }

    extern __shared__ float sm[];
    int tid = threadIdx.x;

    if (blockIdx.x < NETB) {
        // ---- net path: 3 -> 128 -> 128 ----
        float* sW1  = sm;
        float* sb1  = sW1 + 128 * 3;
        float* sW2  = sb1 + 128;          // [c][k] stride 132
        float* sb2  = sW2 + 128 * 132;
        float* sX   = sb2 + 128;
        float* st   = sX + 64 * 4;

        for (int i = tid; i < 128 * 3; i += 512) sW1[i] = nW1[i];
        if (tid < 128) sb1[tid] = nb1[tid];
        for (int i = tid; i < 128 * 128; i += 512) {
            int c = i >> 7, k = i & 127;
            sW2[c * 132 + k] = nW2[i];
        }
        if (tid < 128) sb2[tid] = nb2[tid];
        __syncthreads();

        int rg2 = tid >> 5;
        int cg  = tid & 31;

        int numTiles = (NN + 63) / 64;
        for (int tile = blockIdx.x; tile < numTiles; tile += NETB) {
            int base = tile * 64;
            __syncthreads();
            for (int i = tid; i < 64 * 3; i += 512) {
                int r = i / 3, p = i % 3;
                int row = base + r;
                sX[r * 4 + p] = (row < NN) ? xn[(size_t)row * 3 + p] : 0.f;
            }
            __syncthreads();
            for (int i = tid; i < 64 * 128; i += 512) {
                int r = i >> 7, j = i & 127;
                float a = sb1[j] + sX[r * 4] * sW1[j * 3] + sX[r * 4 + 1] * sW1[j * 3 + 1]
                        + sX[r * 4 + 2] * sW1[j * 3 + 2];
                st[i] = lrelu(a);
            }
            __syncthreads();

            ull acc[4][4];
            #pragma unroll
            for (int r = 0; r < 4; r++)
                #pragma unroll
                for (int j = 0; j < 4; j++) acc[r][j] = 0ull;

            const float* tb = st + rg2 * 4 * 128;
            #pragma unroll 2
            for (int k = 0; k < 128; k += 4) {
                ull w01[4], w23[4];
                #pragma unroll
                for (int j = 0; j < 4; j++) {
                    float4 w = *(const float4*)(sW2 + (cg + 32 * j) * 132 + k);
                    w01[j] = ((ull*)&w)[0]; w23[j] = ((ull*)&w)[1];
                }
                #pragma unroll
                for (int r = 0; r < 4; r++) {
                    float4 h4 = *(const float4*)(tb + r * 128 + k);
                    ull h01 = ((ull*)&h4)[0], h23 = ((ull*)&h4)[1];
                    #pragma unroll
                    for (int j = 0; j < 4; j++) {
                        fma2(acc[r][j], h01, w01[j]);
                        fma2(acc[r][j], h23, w23[j]);
                    }
                }
            }
            #pragma unroll
            for (int r = 0; r < 4; r++) {
                int row = base + rg2 * 4 + r;
                if (row < NN) {
                    #pragma unroll
                    for (int j = 0; j < 4; j++) {
                        int c = cg + 32 * j;
                        float v = lrelu(unpack_sum(acc[r][j]) + sb2[c]);
                        g_h[(size_t)(NI + row) * D + c] = v;
                        out[(size_t)row * 512 + c] = v;
                    }
                }
            }
        }
    } else {
        // ---- instance path: 11 -> 256 -> 128 ----
        float* sW1T = sm;
        float* sb1  = sW1T + 11 * 256;
        float* sW2  = sb1 + 256;          // [c][k] stride 260
        float* sb2  = sW2 + 128 * 260;
        float* sX   = sb2 + 128;
        float* st   = sX + 64 * 12;

        for (int i = tid; i < 256 * 11; i += 512) {
            int j = i / 11, p = i % 11;
            sW1T[p * 256 + j] = W1[i];
        }
        if (tid < 256) sb1[tid] = b1[tid];
        for (int i = tid; i < 128 * 256; i += 512) {
            int c = i >> 8, k = i & 255;
            sW2[c * 260 + k] = W2[i];
        }
        if (tid < 128) sb2[tid] = b2[tid];
        __syncthreads();

        int rg1 = tid >> 6;
        int jg  = tid & 63;
        float4 b1v = *(const float4*)(sb1 + jg * 4);

        int rg2 = tid >> 5;
        int cg  = tid & 31;

        int nb = gridDim.x - NETB;
        int numTiles = (NI + 63) / 64;
        for (int tile = blockIdx.x - NETB; tile < numTiles; tile += nb) {
            int base = tile * 64;
            __syncthreads();
            for (int i = tid; i < 64 * 11; i += 512) {
                int r = i / 11, p = i % 11;
                int row = base + r;
                sX[r * 12 + p] = (row < NI) ? x[(size_t)row * 11 + p] : 0.f;
            }
            __syncthreads();

            {
                float4 acc[8];
                #pragma unroll
                for (int r = 0; r < 8; r++) acc[r] = b1v;
                #pragma unroll
                for (int p = 0; p < 11; p++) {
                    float4 w = *(const float4*)(sW1T + p * 256 + jg * 4);
                    #pragma unroll
                    for (int r = 0; r < 8; r++) {
                        float xv = sX[(rg1 * 8 + r) * 12 + p];
                        acc[r].x += xv * w.x; acc[r].y += xv * w.y;
                        acc[r].z += xv * w.z; acc[r].w += xv * w.w;
                    }
                }
                #pragma unroll
                for (int r = 0; r < 8; r++)
                    *(float4*)(st + (rg1 * 8 + r) * 256 + jg * 4) = lrelu4(acc[r]);
            }
            __syncthreads();

            {
                ull acc[4][4];
                #pragma unroll
                for (int r = 0; r < 4; r++)
                    #pragma unroll
                    for (int j = 0; j < 4; j++) acc[r][j] = 0ull;

                const float* tb = st + rg2 * 4 * 256;
                #pragma unroll 2
                for (int k = 0; k < 256; k += 4) {
                    ull w01[4], w23[4];
                    #pragma unroll
                    for (int j = 0; j < 4; j++) {
                        float4 w = *(const float4*)(sW2 + (cg + 32 * j) * 260 + k);
                        w01[j] = ((ull*)&w)[0]; w23[j] = ((ull*)&w)[1];
                    }
                    #pragma unroll
                    for (int r = 0; r < 4; r++) {
                        float4 h4 = *(const float4*)(tb + r * 256 + k);
                        ull h01 = ((ull*)&h4)[0], h23 = ((ull*)&h4)[1];
                        #pragma unroll
                        for (int j = 0; j < 4; j++) {
                            fma2(acc[r][j], h01, w01[j]);
                            fma2(acc[r][j], h23, w23[j]);
                        }
                    }
                }
                #pragma unroll
                for (int r = 0; r < 4; r++) {
                    int row = base + rg2 * 4 + r;
                    if (row < NI) {
                        #pragma unroll
                        for (int j = 0; j < 4; j++) {
                            int c = cg + 32 * j;
                            float v = lrelu(unpack_sum(acc[r][j]) + sb2[c]);
                            g_h[(size_t)row * D + c] = v;
                        }
                    }
                }
            }
        }
    }
}

// ---------------- degree count ----------------
__global__ void deg_count_kernel(const int* __restrict__ src, const int* __restrict__ dst, int E)
{
    int e = blockIdx.x * blockDim.x + threadIdx.x;
    if (e < E) {
        atomicAdd(&g_deg_in[dst[e]], 1.0f);
        atomicAdd(&g_deg_out[src[e]], 1.0f);
    }
}

// ---------------- scan + fin ----------------
__global__ void scan_fin_kernel(int N, int E)
{
    __shared__ int warp_sums[32];
    __shared__ int warp_offs[32];
    __shared__ int chunk_tot;
    __shared__ int carry_s;
    const float* deg = (blockIdx.x == 0) ? g_deg_in : g_deg_out;
    int* off = (blockIdx.x == 0) ? g_off_in : g_off_out;
    int tid = threadIdx.x, lane = tid & 31, wid = tid >> 5;
    if (tid == 0) carry_s = 0;
    __syncthreads();
    for (int base = 0; base < N; base += 1024) {
        int i = base + tid;
        int v = (i < N) ? ((int)deg[i]) - 1 : 0;
        int incl = v;
        #pragma unroll
        for (int o = 1; o < 32; o <<= 1) {
            int t = __shfl_up_sync(0xffffffffu, incl, o);
            if (lane >= o) incl += t;
        }
        if (lane == 31) warp_sums[wid] = incl;
        __syncthreads();
        if (wid == 0) {
            int ws = warp_sums[lane];
            int wi = ws;
            #pragma unroll
            for (int o = 1; o < 32; o <<= 1) {
                int t = __shfl_up_sync(0xffffffffu, wi, o);
                if (lane >= o) wi += t;
            }
            warp_offs[lane] = wi - ws;
            if (lane == 31) chunk_tot = wi;
        }
        __syncthreads();
        if (i < N) off[i] = carry_s + warp_offs[wid] + incl - v;
        __syncthreads();
        if (tid == 0) carry_s += chunk_tot;
    }
    if (tid == 0) off[N] = E;
    if (blockIdx.x == 0) {
        for (int i = tid; i < N; i += 1024) {
            float a = g_deg_in[i];
            g_dinv_in[i] = rsqrtf(a);
            g_rdeg_in[i] = 1.0f / a;
            g_fill_in[i] = 0;
        }
    } else {
        for (int i = tid; i < N; i += 1024) {
            float a = g_deg_out[i];
            g_dinv_out[i] = rsqrtf(a);
            g_rdeg_out[i] = 1.0f / a;
            g_fill_out[i] = 0;
        }
    }
}

__global__ void fill_kernel(const int* __restrict__ src, const int* __restrict__ dst, int E)
{
    int e = blockIdx.x * blockDim.x + threadIdx.x;
    if (e < E) {
        int s = src[e], d = dst[e];
        int p = atomicAdd(&g_fill_in[d], 1);
        g_csr_in[g_off_in[d] + p] = s;
        int q = atomicAdd(&g_fill_out[s], 1);
        g_csr_out[g_off_out[s] + q] = d;
    }
}

// ---------------- per-layer dense part: mma.sync fp16-split GEMM ----------------
#define PH 136       // smem pitch in halves
#define PB 272       // smem pitch in bytes
#define TILE_B (128 * PB)          // 34816
#define OFF_WF_HI 0
#define OFF_WF_LO (1 * TILE_B)
#define OFF_WR_HI (2 * TILE_B)
#define OFF_WR_LO (3 * TILE_B)
#define OFF_A_HI  (4 * TILE_B)
#define OFF_A_LO  (5 * TILE_B)
#define OFF_BIAS  (6 * TILE_B)     // float[256] (F,R)
#define OFF_ROOT  (6 * TILE_B + 1024)
#define SMEM_MMA  (6 * TILE_B + 2048)   // 210944

__global__ void __launch_bounds__(512, 1)
conv_mma_kernel(const float* __restrict__ Wf, const float* __restrict__ bf,
                const float* __restrict__ rootf,
                const float* __restrict__ Wr, const float* __restrict__ br,
                const float* __restrict__ rootr, int N)
{
    extern __shared__ __align__(16) char smc[];
    uint32_t sbase = smem_u32(smc);
    int tid = threadIdx.x;

    float* sbias = (float*)(smc + OFF_BIAS);
    float* sroot = (float*)(smc + OFF_ROOT);
    if (tid < 128) {
        sbias[tid] = bf[tid];       sbias[128 + tid] = br[tid];
        sroot[tid] = rootf[tid];    sroot[128 + tid] = rootr[tid];
    }
    for (int i = tid; i < 128 * 64; i += 512) {
        int c = i >> 6, k2 = (i & 63) << 1;
        int ho = c * PH + k2;
        float2 wf = *(const float2*)(Wf + c * 128 + k2);
        half2 hf = __float22half2_rn(wf);
        float2 bf2 = __half22float2(hf);
        *(half2*)((__half*)(smc + OFF_WF_HI) + ho) = hf;
        *(half2*)((__half*)(smc + OFF_WF_LO) + ho) =
            __float22half2_rn(make_float2(wf.x - bf2.x, wf.y - bf2.y));
        float2 wr = *(const float2*)(Wr + c * 128 + k2);
        half2 hr = __float22half2_rn(wr);
        float2 br2 = __half22float2(hr);
        *(half2*)((__half*)(smc + OFF_WR_HI) + ho) = hr;
        *(half2*)((__half*)(smc + OFF_WR_LO) + ho) =
            __float22half2_rn(make_float2(wr.x - br2.x, wr.y - br2.y));
    }
    __syncthreads();

    int w = tid >> 5, lane = tid & 31;
    int dir = w >> 3;
    int wm = (w & 7) * 16;

    uint32_t bHiBase = sbase + (dir ? OFF_WR_HI : OFF_WF_HI);
    uint32_t bLoBase = sbase + (dir ? OFF_WR_LO : OFF_WF_LO);

    uint32_t aLaneOff = (uint32_t)((wm + (lane & 15)) * PB + ((lane >> 4) << 4));
    uint32_t bLaneOff = (uint32_t)(((((lane >> 4) << 3) + (lane & 7)) * PB) + ((((lane >> 3) & 1)) << 4));
    uint32_t aHiAddr = sbase + OFF_A_HI + aLaneOff;
    uint32_t aLoAddr = sbase + OFF_A_LO + aLaneOff;
    uint32_t bHiAddr = bHiBase + bLaneOff;
    uint32_t bLoAddr = bLoBase + bLaneOff;

    __half* xout = dir ? g_xr : g_xf;
    float* aout = dir ? g_aggr : g_aggf;
    const float* rdegp = dir ? g_rdeg_out : g_rdeg_in;
    const float* dinvp = dir ? g_dinv_out : g_dinv_in;

    int numTiles = (N + 127) / 128;
    for (int tile = blockIdx.x; tile < numTiles; tile += gridDim.x) {
        int base = tile * 128;
        __syncthreads();
        for (int i = tid; i < 128 * 64; i += 512) {
            int r = i >> 6, k2 = (i & 63) << 1;
            int row = base + r;
            float2 v = (row < N) ? *(const float2*)(g_h + (size_t)row * D + k2)
                                 : make_float2(0.f, 0.f);
            half2 h2 = __float22half2_rn(v);
            float2 bk = __half22float2(h2);
            int ho = r * PH + k2;
            *(half2*)((__half*)(smc + OFF_A_HI) + ho) = h2;
            *(half2*)((__half*)(smc + OFF_A_LO) + ho) =
                __float22half2_rn(make_float2(v.x - bk.x, v.y - bk.y));
        }
        __syncthreads();

        float acc[16][4];
        #pragma unroll
        for (int nf = 0; nf < 16; nf++)
            #pragma unroll
            for (int j = 0; j < 4; j++) acc[nf][j] = 0.f;

        #pragma unroll 1
        for (int kf = 0; kf < 8; kf++) {
            uint32_t ko = kf * 32;
            uint32_t ah[4], al[4];
            ldsm4(ah, aHiAddr + ko);
            ldsm4(al, aLoAddr + ko);
            #pragma unroll
            for (int nb = 0; nb < 8; nb++) {
                uint32_t boff = (uint32_t)(nb * 16 * PB) + ko;
                uint32_t bh[4], bl[4];
                ldsm4(bh, bHiAddr + boff);
                ldsm4(bl, bLoAddr + boff);
                mma16816(acc[nb * 2],     ah, bh[0], bh[1]);
                mma16816(acc[nb * 2],     ah, bl[0], bl[1]);
                mma16816(acc[nb * 2],     al, bh[0], bh[1]);
                mma16816(acc[nb * 2 + 1], ah, bh[2], bh[3]);
                mma16816(acc[nb * 2 + 1], ah, bl[2], bl[3]);
                mma16816(acc[nb * 2 + 1], al, bh[2], bh[3]);
            }
        }

        int g = lane >> 2, t4 = lane & 3;
        int row0 = base + wm + g;
        int row1 = row0 + 8;
        float di0 = 0.f, rd0 = 0.f, di1 = 0.f, rd1 = 0.f;
        if (row0 < N) { di0 = dinvp[row0]; rd0 = rdegp[row0]; }
        if (row1 < N) { di1 = dinvp[row1]; rd1 = rdegp[row1]; }
        #pragma unroll
        for (int nf = 0; nf < 16; nf++) {
            int col = nf * 8 + t4 * 2;
            float2 bb = *(const float2*)(sbias + dir * 128 + col);
            float2 rr = *(const float2*)(sroot + dir * 128 + col);
            if (row0 < N) {
                float v0 = acc[nf][0] + bb.x, v1 = acc[nf][1] + bb.y;
                half2 xh = __floats2half2_rn(fmaxf(v0, 0.f) * di0, fmaxf(v1, 0.f) * di0);
                *(half2*)(xout + (size_t)row0 * D + col) = xh;
                *(float2*)(aout + (size_t)row0 * D + col) =
                    make_float2(fmaxf(v0 + rr.x, 0.f) * rd0, fmaxf(v1 + rr.y, 0.f) * rd0);
            }
            if (row1 < N) {
                float v2 = acc[nf][2] + bb.x, v3 = acc[nf][3] + bb.y;
                half2 xh = __floats2half2_rn(fmaxf(v2, 0.f) * di1, fmaxf(v3, 0.f) * di1);
                *(half2*)(xout + (size_t)row1 * D + col) = xh;
                *(float2*)(aout + (size_t)row1 * D + col) =
                    make_float2(fmaxf(v2 + rr.x, 0.f) * rd1, fmaxf(v3 + rr.y, 0.f) * rd1);
            }
        }
    }
}

// ---------------- fused gather: 2 warps per node (one per direction) + LN + residual ----------------
// Per warp: 2 neighbors/iter, 16B loads (lane half/l16 split as R11). Rev warp deposits
// its contribution (agg + dinv*sum) in smem; fwd warp combines, LN, residual, store.
__device__ __forceinline__ void gather_dir_2n(const int* __restrict__ csr, int s0, int s1,
                                              const __half* __restrict__ xs,
                                              int half, int l16, float* acc8)
{
    for (int j = s0; j < s1; j += 32) {
        int nn = s1 - j; if (nn > 32) nn = 32;
        int lane = half * 16 + l16;
        int idx = (lane < nn) ? csr[j + lane] : 0;
        if (nn == 32) {
            #pragma unroll
            for (int k = 0; k < 16; k++) {
                int id = __shfl_sync(0xffffffffu, idx, 2 * k + half);
                uint4 v = *(const uint4*)(xs + (size_t)id * D + l16 * 8);
                float2 f0 = __half22float2(*(half2*)&v.x);
                float2 f1 = __half22float2(*(half2*)&v.y);
                float2 f2 = __half22float2(*(half2*)&v.z);
                float2 f3 = __half22float2(*(half2*)&v.w);
                acc8[0] += f0.x; acc8[1] += f0.y; acc8[2] += f1.x; acc8[3] += f1.y;
                acc8[4] += f2.x; acc8[5] += f2.y; acc8[6] += f3.x; acc8[7] += f3.y;
            }
        } else {
            int pairs = (nn + 1) >> 1;
            for (int k = 0; k < pairs; k++) {
                int slot = 2 * k + half;
                int id = __shfl_sync(0xffffffffu, idx, slot < nn ? slot : 0);
                if (slot < nn) {
                    uint4 v = *(const uint4*)(xs + (size_t)id * D + l16 * 8);
                    float2 f0 = __half22float2(*(half2*)&v.x);
                    float2 f1 = __half22float2(*(half2*)&v.y);
                    float2 f2 = __half22float2(*(half2*)&v.z);
                    float2 f3 = __half22float2(*(half2*)&v.w);
                    acc8[0] += f0.x; acc8[1] += f0.y; acc8[2] += f1.x; acc8[3] += f1.y;
                    acc8[4] += f2.x; acc8[5] += f2.y; acc8[6] += f3.x; acc8[7] += f3.y;
                }
            }
        }
    }
}

__device__ __forceinline__ float4 combine_halves(const float* acc8, int half)
{
    float r[4];
    #pragma unroll
    for (int m = 0; m < 4; m++) {
        float send = half ? acc8[m] : acc8[4 + m];
        float recv = __shfl_xor_sync(0xffffffffu, send, 16);
        float keep = half ? acc8[4 + m] : acc8[m];
        r[m] = keep + recv;
    }
    return make_float4(r[0], r[1], r[2], r[3]);
}

// block = 256 threads = 8 warps = 4 nodes; warp pair {2i (fwd), 2i+1 (rev)} per node.
__global__ void __launch_bounds__(256)
gather_post_kernel(const float* __restrict__ lng, const float* __restrict__ lnb,
                   float* __restrict__ out, int NI, int N, int l)
{
    __shared__ float s_rev[4][128];

    int widx = threadIdx.x >> 5;
    int lane = threadIdx.x & 31;
    int nodeLocal = widx >> 1;
    int dir = widx & 1;
    int n = blockIdx.x * 4 + nodeLocal;
    bool active = (n < N);

    int half = lane >> 4, l16 = lane & 15;
    int colb = l16 * 8 + half * 4;      // this lane's 4-col slice (permuted partition)

    float4 contrib = make_float4(0.f, 0.f, 0.f, 0.f);
    if (active) {
        const int* csr   = dir ? g_csr_out : g_csr_in;
        const int* off   = dir ? g_off_out : g_off_in;
        const __half* xs = dir ? g_xr : g_xf;
        const float* dinv = dir ? g_dinv_out : g_dinv_in;
        const float* agg  = dir ? g_aggr : g_aggf;

        int s0 = off[n], s1 = off[n + 1];
        float acc8[8];
        #pragma unroll
        for (int j = 0; j < 8; j++) acc8[j] = 0.f;
        gather_dir_2n(csr, s0, s1, xs, half, l16, acc8);
        float4 sv = combine_halves(acc8, half);

        float dv = dinv[n];
        float4 ag = *(const float4*)(agg + (size_t)n * D + colb);
        contrib.x = ag.x + sv.x * dv;
        contrib.y = ag.y + sv.y * dv;
        contrib.z = ag.z + sv.z * dv;
        contrib.w = ag.w + sv.w * dv;

        if (dir == 1)
            *(float4*)(&s_rev[nodeLocal][colb]) = contrib;
    }
    __syncthreads();

    if (!active || dir == 1) return;

    float4 o = *(const float4*)(&s_rev[nodeLocal][colb]);
    float4 s;
    s.x = contrib.x + o.x;
    s.y = contrib.y + o.y;
    s.z = contrib.z + o.z;
    s.w = contrib.w + o.w;

    float sum = s.x + s.y + s.z + s.w;
    #pragma unroll
    for (int o2 = 16; o2; o2 >>= 1) sum += __shfl_xor_sync(0xffffffffu, sum, o2);
    float mu = sum * (1.0f / 128.0f);

    float dx = s.x - mu, dy = s.y - mu, dz = s.z - mu, dw = s.w - mu;
    float sq = dx * dx + dy * dy + dz * dz + dw * dw;
    #pragma unroll
    for (int o2 = 16; o2; o2 >>= 1) sq += __shfl_xor_sync(0xffffffffu, sq, o2);
    float rs = rsqrtf(sq * (1.0f / 128.0f) + 1e-5f);

    float4 gg = *(const float4*)(lng + colb);
    float4 bb = *(const float4*)(lnb + colb);
    float4 y;
    y.x = lrelu(dx * rs * gg.x + bb.x);
    y.y = lrelu(dy * rs * gg.y + bb.y);
    y.z = lrelu(dz * rs * gg.z + bb.z);
    y.w = lrelu(dw * rs * gg.w + bb.w);

    float4 h = *(const float4*)(g_h + (size_t)n * D + colb);
    h.x += y.x; h.y += y.y; h.z += y.z; h.w += y.w;
    *(float4*)(g_h + (size_t)n * D + colb) = h;

    if (n >= NI) {
        *(float4*)(out + (size_t)(n - NI) * 512 + (size_t)(l + 1) * 128 + colb) = h;
    }
}

// ---------------- launch ----------------
extern "C" void kernel_launch(void* const* d_in, const int* in_sizes, int n_in,
                              void* d_out, int out_size)
{
    const float* x      = (const float*)d_in[0];
    const float* xnet   = (const float*)d_in[1];
    const float* encW1  = (const float*)d_in[2];
    const float* encb1  = (const float*)d_in[3];
    const float* encW2  = (const float*)d_in[4];
    const float* encb2  = (const float*)d_in[5];
    const float* encnW1 = (const float*)d_in[6];
    const float* encnb1 = (const float*)d_in[7];
    const float* encnW2 = (const float*)d_in[8];
    const float* encnb2 = (const float*)d_in[9];
    const float* convW  = (const float*)d_in[10];
    const float* convb  = (const float*)d_in[11];
    const float* convr  = (const float*)d_in[12];
    const float* rconvW = (const float*)d_in[13];
    const float* rconvb = (const float*)d_in[14];
    const float* rconvr = (const float*)d_in[15];
    const float* lng    = (const float*)d_in[16];
    const float* lnb    = (const float*)d_in[17];
    const int*   src    = (const int*)d_in[18];
    const int*   dst    = (const int*)d_in[19];

    int NI = in_sizes[0] / 11;
    int NN = in_sizes[1] / 3;
    int N  = NI + NN;
    int E  = in_sizes[18];
    float* out = (float*)d_out;

    size_t sm1 = (size_t)(11 * 256 + 256 + 128 * 260 + 128 + 64 * 12 + 64 * 256) * 4;
    cudaFuncSetAttribute(enc_kernel, cudaFuncAttributeMaxDynamicSharedMemorySize, (int)sm1);
    cudaFuncSetAttribute(conv_mma_kernel, cudaFuncAttributeMaxDynamicSharedMemorySize, SMEM_MMA);

    enc_kernel<<<148, 512, sm1>>>(x, xnet, encW1, encb1, encW2, encb2,
                                  encnW1, encnb1, encnW2, encnb2, NI, NN, N, out);
    deg_count_kernel<<<(E + 255) / 256, 256>>>(src, dst, E);
    scan_fin_kernel<<<2, 1024>>>(N, E);
    conv_mma_kernel<<<148, 512, SMEM_MMA>>>(convW, convb, convr, rconvW, rconvb, rconvr, N);
    fill_kernel<<<(E + 255) / 256, 256>>>(src, dst, E);

    int gp_blocks = (N + 3) / 4;
    gather_post_kernel<<<gp_blocks, 256>>>(lng, lnb, out, NI, N, 0);

    for (int l = 1; l < 3; l++) {
        conv_mma_kernel<<<148, 512, SMEM_MMA>>>(convW + (size_t)l * 16384, convb + l * 128, convr + l * 128,
                                                rconvW + (size_t)l * 16384, rconvb + l * 128, rconvr + l * 128, N);
        gather_post_kernel<<<gp_blocks, 256>>>(lng + l * 128, lnb + l * 128, out, NI, N, l);
    }
}

// round 13
// speedup vs baseline: 1.0382x; 1.0382x over previous
#include <cuda_runtime.h>
#include <cuda_fp16.h>
#include <cstdint>

#define D 128
#define NMAX 50176
#define EMAX 1048576

typedef unsigned long long ull;

// ---------------- scratch ----------------
static __device__ float g_h[NMAX * D];
static __device__ __align__(16) __half g_xf[NMAX * D];   // dinv_in*relu(xf), fp16
static __device__ __align__(16) __half g_xr[NMAX * D];   // dinv_out*relu(xr), fp16
static __device__ float g_aggf[NMAX * D];
static __device__ float g_aggr[NMAX * D];
static __device__ float g_deg_in[NMAX];
static __device__ float g_deg_out[NMAX];
static __device__ float g_dinv_in[NMAX];
static __device__ float g_dinv_out[NMAX];
static __device__ float g_rdeg_in[NMAX];
static __device__ float g_rdeg_out[NMAX];
static __device__ int g_off_in[NMAX + 1];
static __device__ int g_off_out[NMAX + 1];
static __device__ int g_fill_in[NMAX];
static __device__ int g_fill_out[NMAX];
static __device__ int g_csr_in[EMAX];
static __device__ int g_csr_out[EMAX];

__device__ __forceinline__ float lrelu(float v) { return v >= 0.f ? v : 0.1f * v; }
__device__ __forceinline__ float4 lrelu4(float4 v) {
    return make_float4(lrelu(v.x), lrelu(v.y), lrelu(v.z), lrelu(v.w));
}
__device__ __forceinline__ void fma2(ull& d, ull a, ull b) {
    asm("fma.rn.f32x2 %0, %1, %2, %0;" : "+l"(d) : "l"(a), "l"(b));
}
__device__ __forceinline__ float unpack_sum(ull v) {
    float2 p = *(float2*)&v;
    return p.x + p.y;
}

// ---------------- mma.sync helpers ----------------
__device__ __forceinline__ uint32_t smem_u32(const void* p) {
    uint32_t a;
    asm("{ .reg .u64 t; cvta.to.shared.u64 t, %1; cvt.u32.u64 %0, t; }" : "=r"(a) : "l"(p));
    return a;
}
__device__ __forceinline__ void ldsm4(uint32_t* r, uint32_t addr) {
    asm volatile("ldmatrix.sync.aligned.m8n8.x4.shared.b16 {%0,%1,%2,%3}, [%4];"
                 : "=r"(r[0]), "=r"(r[1]), "=r"(r[2]), "=r"(r[3]) : "r"(addr));
}
__device__ __forceinline__ void mma16816(float* c, const uint32_t* a, uint32_t b0, uint32_t b1) {
    asm volatile("mma.sync.aligned.m16n8k16.row.col.f32.f16.f16.f32 "
                 "{%0,%1,%2,%3}, {%4,%5,%6,%7}, {%8,%9}, {%0,%1,%2,%3};"
                 : "+f"(c[0]), "+f"(c[1]), "+f"(c[2]), "+f"(c[3])
                 : "r"(a[0]), "r"(a[1]), "r"(a[2]), "r"(a[3]), "r"(b0), "r"(b1));
}

#define NETB 16

// ---------------- fused encoders (+ degree init) ----------------
__global__ void __launch_bounds__(512, 1)
enc_kernel(const float* __restrict__ x, const float* __restrict__ xn,
           const float* __restrict__ W1, const float* __restrict__ b1,
           const float* __restrict__ W2, const float* __restrict__ b2,
           const float* __restrict__ nW1, const float* __restrict__ nb1,
           const float* __restrict__ nW2, const float* __restrict__ nb2,
           int NI, int NN, int N, float* __restrict__ out)
{
    for (int i = blockIdx.x * 512 + threadIdx.x; i < N; i += gridDim.x * 512) {
        g_deg_in[i] = 1.0f; g_deg_out[i] = 1.0f;
    }

    extern __shared__ float sm[];
    int tid = threadIdx.x;

    if (blockIdx.x < NETB) {
        // ---- net path: 3 -> 128 -> 128 ----
        float* sW1  = sm;
        float* sb1  = sW1 + 128 * 3;
        float* sW2  = sb1 + 128;          // [c][k] stride 132
        float* sb2  = sW2 + 128 * 132;
        float* sX   = sb2 + 128;
        float* st   = sX + 64 * 4;

        for (int i = tid; i < 128 * 3; i += 512) sW1[i] = nW1[i];
        if (tid < 128) sb1[tid] = nb1[tid];
        for (int i = tid; i < 128 * 128; i += 512) {
            int c = i >> 7, k = i & 127;
            sW2[c * 132 + k] = nW2[i];
        }
        if (tid < 128) sb2[tid] = nb2[tid];
        __syncthreads();

        int rg2 = tid >> 5;
        int cg  = tid & 31;

        int numTiles = (NN + 63) / 64;
        for (int tile = blockIdx.x; tile < numTiles; tile += NETB) {
            int base = tile * 64;
            __syncthreads();
            for (int i = tid; i < 64 * 3; i += 512) {
                int r = i / 3, p = i % 3;
                int row = base + r;
                sX[r * 4 + p] = (row < NN) ? xn[(size_t)row * 3 + p] : 0.f;
            }
            __syncthreads();
            for (int i = tid; i < 64 * 128; i += 512) {
                int r = i >> 7, j = i & 127;
                float a = sb1[j] + sX[r * 4] * sW1[j * 3] + sX[r * 4 + 1] * sW1[j * 3 + 1]
                        + sX[r * 4 + 2] * sW1[j * 3 + 2];
                st[i] = lrelu(a);
            }
            __syncthreads();

            ull acc[4][4];
            #pragma unroll
            for (int r = 0; r < 4; r++)
                #pragma unroll
                for (int j = 0; j < 4; j++) acc[r][j] = 0ull;

            const float* tb = st + rg2 * 4 * 128;
            #pragma unroll 2
            for (int k = 0; k < 128; k += 4) {
                ull w01[4], w23[4];
                #pragma unroll
                for (int j = 0; j < 4; j++) {
                    float4 w = *(const float4*)(sW2 + (cg + 32 * j) * 132 + k);
                    w01[j] = ((ull*)&w)[0]; w23[j] = ((ull*)&w)[1];
                }
                #pragma unroll
                for (int r = 0; r < 4; r++) {
                    float4 h4 = *(const float4*)(tb + r * 128 + k);
                    ull h01 = ((ull*)&h4)[0], h23 = ((ull*)&h4)[1];
                    #pragma unroll
                    for (int j = 0; j < 4; j++) {
                        fma2(acc[r][j], h01, w01[j]);
                        fma2(acc[r][j], h23, w23[j]);
                    }
                }
            }
            #pragma unroll
            for (int r = 0; r < 4; r++) {
                int row = base + rg2 * 4 + r;
                if (row < NN) {
                    #pragma unroll
                    for (int j = 0; j < 4; j++) {
                        int c = cg + 32 * j;
                        float v = lrelu(unpack_sum(acc[r][j]) + sb2[c]);
                        g_h[(size_t)(NI + row) * D + c] = v;
                        out[(size_t)row * 512 + c] = v;
                    }
                }
            }
        }
    } else {
        // ---- instance path: 11 -> 256 -> 128 ----
        float* sW1T = sm;
        float* sb1  = sW1T + 11 * 256;
        float* sW2  = sb1 + 256;          // [c][k] stride 260
        float* sb2  = sW2 + 128 * 260;
        float* sX   = sb2 + 128;
        float* st   = sX + 64 * 12;

        for (int i = tid; i < 256 * 11; i += 512) {
            int j = i / 11, p = i % 11;
            sW1T[p * 256 + j] = W1[i];
        }
        if (tid < 256) sb1[tid] = b1[tid];
        for (int i = tid; i < 128 * 256; i += 512) {
            int c = i >> 8, k = i & 255;
            sW2[c * 260 + k] = W2[i];
        }
        if (tid < 128) sb2[tid] = b2[tid];
        __syncthreads();

        int rg1 = tid >> 6;
        int jg  = tid & 63;
        float4 b1v = *(const float4*)(sb1 + jg * 4);

        int rg2 = tid >> 5;
        int cg  = tid & 31;

        int nb = gridDim.x - NETB;
        int numTiles = (NI + 63) / 64;
        for (int tile = blockIdx.x - NETB; tile < numTiles; tile += nb) {
            int base = tile * 64;
            __syncthreads();
            for (int i = tid; i < 64 * 11; i += 512) {
                int r = i / 11, p = i % 11;
                int row = base + r;
                sX[r * 12 + p] = (row < NI) ? x[(size_t)row * 11 + p] : 0.f;
            }
            __syncthreads();

            {
                float4 acc[8];
                #pragma unroll
                for (int r = 0; r < 8; r++) acc[r] = b1v;
                #pragma unroll
                for (int p = 0; p < 11; p++) {
                    float4 w = *(const float4*)(sW1T + p * 256 + jg * 4);
                    #pragma unroll
                    for (int r = 0; r < 8; r++) {
                        float xv = sX[(rg1 * 8 + r) * 12 + p];
                        acc[r].x += xv * w.x; acc[r].y += xv * w.y;
                        acc[r].z += xv * w.z; acc[r].w += xv * w.w;
                    }
                }
                #pragma unroll
                for (int r = 0; r < 8; r++)
                    *(float4*)(st + (rg1 * 8 + r) * 256 + jg * 4) = lrelu4(acc[r]);
            }
            __syncthreads();

            {
                ull acc[4][4];
                #pragma unroll
                for (int r = 0; r < 4; r++)
                    #pragma unroll
                    for (int j = 0; j < 4; j++) acc[r][j] = 0ull;

                const float* tb = st + rg2 * 4 * 256;
                #pragma unroll 2
                for (int k = 0; k < 256; k += 4) {
                    ull w01[4], w23[4];
                    #pragma unroll
                    for (int j = 0; j < 4; j++) {
                        float4 w = *(const float4*)(sW2 + (cg + 32 * j) * 260 + k);
                        w01[j] = ((ull*)&w)[0]; w23[j] = ((ull*)&w)[1];
                    }
                    #pragma unroll
                    for (int r = 0; r < 4; r++) {
                        float4 h4 = *(const float4*)(tb + r * 256 + k);
                        ull h01 = ((ull*)&h4)[0], h23 = ((ull*)&h4)[1];
                        #pragma unroll
                        for (int j = 0; j < 4; j++) {
                            fma2(acc[r][j], h01, w01[j]);
                            fma2(acc[r][j], h23, w23[j]);
                        }
                    }
                }
                #pragma unroll
                for (int r = 0; r < 4; r++) {
                    int row = base + rg2 * 4 + r;
                    if (row < NI) {
                        #pragma unroll
                        for (int j = 0; j < 4; j++) {
                            int c = cg + 32 * j;
                            float v = lrelu(unpack_sum(acc[r][j]) + sb2[c]);
                            g_h[(size_t)row * D + c] = v;
                        }
                    }
                }
            }
        }
    }
}

// ---------------- degree count ----------------
__global__ void deg_count_kernel(const int* __restrict__ src, const int* __restrict__ dst, int E)
{
    int e = blockIdx.x * blockDim.x + threadIdx.x;
    if (e < E) {
        atomicAdd(&g_deg_in[dst[e]], 1.0f);
        atomicAdd(&g_deg_out[src[e]], 1.0f);
    }
}

// ---------------- scan + fin ----------------
__global__ void scan_fin_kernel(int N, int E)
{
    __shared__ int warp_sums[32];
    __shared__ int warp_offs[32];
    __shared__ int chunk_tot;
    __shared__ int carry_s;
    const float* deg = (blockIdx.x == 0) ? g_deg_in : g_deg_out;
    int* off = (blockIdx.x == 0) ? g_off_in : g_off_out;
    int tid = threadIdx.x, lane = tid & 31, wid = tid >> 5;
    if (tid == 0) carry_s = 0;
    __syncthreads();
    for (int base = 0; base < N; base += 1024) {
        int i = base + tid;
        int v = (i < N) ? ((int)deg[i]) - 1 : 0;
        int incl = v;
        #pragma unroll
        for (int o = 1; o < 32; o <<= 1) {
            int t = __shfl_up_sync(0xffffffffu, incl, o);
            if (lane >= o) incl += t;
        }
        if (lane == 31) warp_sums[wid] = incl;
        __syncthreads();
        if (wid == 0) {
            int ws = warp_sums[lane];
            int wi = ws;
            #pragma unroll
            for (int o = 1; o < 32; o <<= 1) {
                int t = __shfl_up_sync(0xffffffffu, wi, o);
                if (lane >= o) wi += t;
            }
            warp_offs[lane] = wi - ws;
            if (lane == 31) chunk_tot = wi;
        }
        __syncthreads();
        if (i < N) off[i] = carry_s + warp_offs[wid] + incl - v;
        __syncthreads();
        if (tid == 0) carry_s += chunk_tot;
    }
    if (tid == 0) off[N] = E;
    if (blockIdx.x == 0) {
        for (int i = tid; i < N; i += 1024) {
            float a = g_deg_in[i];
            g_dinv_in[i] = rsqrtf(a);
            g_rdeg_in[i] = 1.0f / a;
            g_fill_in[i] = 0;
        }
    } else {
        for (int i = tid; i < N; i += 1024) {
            float a = g_deg_out[i];
            g_dinv_out[i] = rsqrtf(a);
            g_rdeg_out[i] = 1.0f / a;
            g_fill_out[i] = 0;
        }
    }
}

__global__ void fill_kernel(const int* __restrict__ src, const int* __restrict__ dst, int E)
{
    int e = blockIdx.x * blockDim.x + threadIdx.x;
    if (e < E) {
        int s = src[e], d = dst[e];
        int p = atomicAdd(&g_fill_in[d], 1);
        g_csr_in[g_off_in[d] + p] = s;
        int q = atomicAdd(&g_fill_out[s], 1);
        g_csr_out[g_off_out[s] + q] = d;
    }
}

// ---------------- per-layer dense part: mma.sync 2-term fp16-split GEMM ----------------
// x = A_hi*(W_hi + W_lo); dropped A_lo term contributes ~3e-4 relative (random-sign sums).
#define PH 136       // smem pitch in halves
#define PB 272       // smem pitch in bytes
#define TILE_B (128 * PB)          // 34816
#define OFF_WF_HI 0
#define OFF_WF_LO (1 * TILE_B)
#define OFF_WR_HI (2 * TILE_B)
#define OFF_WR_LO (3 * TILE_B)
#define OFF_A_HI  (4 * TILE_B)
#define OFF_BIAS  (5 * TILE_B)     // float[256] (F,R)
#define OFF_ROOT  (5 * TILE_B + 1024)
#define SMEM_MMA  (5 * TILE_B + 2048)   // 176128

__global__ void __launch_bounds__(512, 1)
conv_mma_kernel(const float* __restrict__ Wf, const float* __restrict__ bf,
                const float* __restrict__ rootf,
                const float* __restrict__ Wr, const float* __restrict__ br,
                const float* __restrict__ rootr, int N)
{
    extern __shared__ __align__(16) char smc[];
    uint32_t sbase = smem_u32(smc);
    int tid = threadIdx.x;

    float* sbias = (float*)(smc + OFF_BIAS);
    float* sroot = (float*)(smc + OFF_ROOT);
    if (tid < 128) {
        sbias[tid] = bf[tid];       sbias[128 + tid] = br[tid];
        sroot[tid] = rootf[tid];    sroot[128 + tid] = rootr[tid];
    }
    for (int i = tid; i < 128 * 64; i += 512) {
        int c = i >> 6, k2 = (i & 63) << 1;
        int ho = c * PH + k2;
        float2 wf = *(const float2*)(Wf + c * 128 + k2);
        half2 hf = __float22half2_rn(wf);
        float2 bf2 = __half22float2(hf);
        *(half2*)((__half*)(smc + OFF_WF_HI) + ho) = hf;
        *(half2*)((__half*)(smc + OFF_WF_LO) + ho) =
            __float22half2_rn(make_float2(wf.x - bf2.x, wf.y - bf2.y));
        float2 wr = *(const float2*)(Wr + c * 128 + k2);
        half2 hr = __float22half2_rn(wr);
        float2 br2 = __half22float2(hr);
        *(half2*)((__half*)(smc + OFF_WR_HI) + ho) = hr;
        *(half2*)((__half*)(smc + OFF_WR_LO) + ho) =
            __float22half2_rn(make_float2(wr.x - br2.x, wr.y - br2.y));
    }
    __syncthreads();

    int w = tid >> 5, lane = tid & 31;
    int dir = w >> 3;
    int wm = (w & 7) * 16;

    uint32_t bHiBase = sbase + (dir ? OFF_WR_HI : OFF_WF_HI);
    uint32_t bLoBase = sbase + (dir ? OFF_WR_LO : OFF_WF_LO);

    uint32_t aLaneOff = (uint32_t)((wm + (lane & 15)) * PB + ((lane >> 4) << 4));
    uint32_t bLaneOff = (uint32_t)(((((lane >> 4) << 3) + (lane & 7)) * PB) + ((((lane >> 3) & 1)) << 4));
    uint32_t aHiAddr = sbase + OFF_A_HI + aLaneOff;
    uint32_t bHiAddr = bHiBase + bLaneOff;
    uint32_t bLoAddr = bLoBase + bLaneOff;

    __half* xout = dir ? g_xr : g_xf;
    float* aout = dir ? g_aggr : g_aggf;
    const float* rdegp = dir ? g_rdeg_out : g_rdeg_in;
    const float* dinvp = dir ? g_dinv_out : g_dinv_in;

    int numTiles = (N + 127) / 128;
    for (int tile = blockIdx.x; tile < numTiles; tile += gridDim.x) {
        int base = tile * 128;
        __syncthreads();
        // stage A_hi only
        for (int i = tid; i < 128 * 64; i += 512) {
            int r = i >> 6, k2 = (i & 63) << 1;
            int row = base + r;
            float2 v = (row < N) ? *(const float2*)(g_h + (size_t)row * D + k2)
                                 : make_float2(0.f, 0.f);
            *(half2*)((__half*)(smc + OFF_A_HI) + r * PH + k2) = __float22half2_rn(v);
        }
        __syncthreads();

        float acc[16][4];
        #pragma unroll
        for (int nf = 0; nf < 16; nf++)
            #pragma unroll
            for (int j = 0; j < 4; j++) acc[nf][j] = 0.f;

        #pragma unroll 1
        for (int kf = 0; kf < 8; kf++) {
            uint32_t ko = kf * 32;
            uint32_t ah[4];
            ldsm4(ah, aHiAddr + ko);
            #pragma unroll
            for (int nb = 0; nb < 8; nb++) {
                uint32_t boff = (uint32_t)(nb * 16 * PB) + ko;
                uint32_t bh[4], bl[4];
                ldsm4(bh, bHiAddr + boff);
                ldsm4(bl, bLoAddr + boff);
                mma16816(acc[nb * 2],     ah, bh[0], bh[1]);
                mma16816(acc[nb * 2],     ah, bl[0], bl[1]);
                mma16816(acc[nb * 2 + 1], ah, bh[2], bh[3]);
                mma16816(acc[nb * 2 + 1], ah, bl[2], bl[3]);
            }
        }

        int g = lane >> 2, t4 = lane & 3;
        int row0 = base + wm + g;
        int row1 = row0 + 8;
        float di0 = 0.f, rd0 = 0.f, di1 = 0.f, rd1 = 0.f;
        if (row0 < N) { di0 = dinvp[row0]; rd0 = rdegp[row0]; }
        if (row1 < N) { di1 = dinvp[row1]; rd1 = rdegp[row1]; }
        #pragma unroll
        for (int nf = 0; nf < 16; nf++) {
            int col = nf * 8 + t4 * 2;
            float2 bb = *(const float2*)(sbias + dir * 128 + col);
            float2 rr = *(const float2*)(sroot + dir * 128 + col);
            if (row0 < N) {
                float v0 = acc[nf][0] + bb.x, v1 = acc[nf][1] + bb.y;
                half2 xh = __floats2half2_rn(fmaxf(v0, 0.f) * di0, fmaxf(v1, 0.f) * di0);
                *(half2*)(xout + (size_t)row0 * D + col) = xh;
                *(float2*)(aout + (size_t)row0 * D + col) =
                    make_float2(fmaxf(v0 + rr.x, 0.f) * rd0, fmaxf(v1 + rr.y, 0.f) * rd0);
            }
            if (row1 < N) {
                float v2 = acc[nf][2] + bb.x, v3 = acc[nf][3] + bb.y;
                half2 xh = __floats2half2_rn(fmaxf(v2, 0.f) * di1, fmaxf(v3, 0.f) * di1);
                *(half2*)(xout + (size_t)row1 * D + col) = xh;
                *(float2*)(aout + (size_t)row1 * D + col) =
                    make_float2(fmaxf(v2 + rr.x, 0.f) * rd1, fmaxf(v3 + rr.y, 0.f) * rd1);
            }
        }
    }
}

// ---------------- fused gather (R11 version: 1 warp/node, 2 neighbors/iter) ----------------
__device__ __forceinline__ void gather_dir_2n(const int* __restrict__ csr, int s0, int s1,
                                              const __half* __restrict__ xs,
                                              int half, int l16, float* acc8)
{
    for (int j = s0; j < s1; j += 32) {
        int nn = s1 - j; if (nn > 32) nn = 32;
        int lane = half * 16 + l16;
        int idx = (lane < nn) ? csr[j + lane] : 0;
        if (nn == 32) {
            #pragma unroll
            for (int k = 0; k < 16; k++) {
                int id = __shfl_sync(0xffffffffu, idx, 2 * k + half);
                uint4 v = *(const uint4*)(xs + (size_t)id * D + l16 * 8);
                float2 f0 = __half22float2(*(half2*)&v.x);
                float2 f1 = __half22float2(*(half2*)&v.y);
                float2 f2 = __half22float2(*(half2*)&v.z);
                float2 f3 = __half22float2(*(half2*)&v.w);
                acc8[0] += f0.x; acc8[1] += f0.y; acc8[2] += f1.x; acc8[3] += f1.y;
                acc8[4] += f2.x; acc8[5] += f2.y; acc8[6] += f3.x; acc8[7] += f3.y;
            }
        } else {
            int pairs = (nn + 1) >> 1;
            for (int k = 0; k < pairs; k++) {
                int slot = 2 * k + half;
                int id = __shfl_sync(0xffffffffu, idx, slot < nn ? slot : 0);
                if (slot < nn) {
                    uint4 v = *(const uint4*)(xs + (size_t)id * D + l16 * 8);
                    float2 f0 = __half22float2(*(half2*)&v.x);
                    float2 f1 = __half22float2(*(half2*)&v.y);
                    float2 f2 = __half22float2(*(half2*)&v.z);
                    float2 f3 = __half22float2(*(half2*)&v.w);
                    acc8[0] += f0.x; acc8[1] += f0.y; acc8[2] += f1.x; acc8[3] += f1.y;
                    acc8[4] += f2.x; acc8[5] += f2.y; acc8[6] += f3.x; acc8[7] += f3.y;
                }
            }
        }
    }
}

__device__ __forceinline__ float4 combine_halves(const float* acc8, int half)
{
    float r[4];
    #pragma unroll
    for (int m = 0; m < 4; m++) {
        float send = half ? acc8[m] : acc8[4 + m];
        float recv = __shfl_xor_sync(0xffffffffu, send, 16);
        float keep = half ? acc8[4 + m] : acc8[m];
        r[m] = keep + recv;
    }
    return make_float4(r[0], r[1], r[2], r[3]);
}

__global__ void gather_post_kernel(const float* __restrict__ lng, const float* __restrict__ lnb,
                                   float* __restrict__ out, int NI, int N, int l)
{
    int gt = blockIdx.x * blockDim.x + threadIdx.x;
    int n = gt >> 5, lane = gt & 31;
    if (n >= N) return;
    int half = lane >> 4, l16 = lane & 15;
    int colb = l16 * 8 + half * 4;      // this lane's 4-col slice (permuted partition)

    int si0 = g_off_in[n],  si1 = g_off_in[n + 1];
    int so0 = g_off_out[n], so1 = g_off_out[n + 1];
    float ci = g_dinv_in[n], co = g_dinv_out[n];

    float af8[8], ar8[8];
    #pragma unroll
    for (int j = 0; j < 8; j++) { af8[j] = 0.f; ar8[j] = 0.f; }

    gather_dir_2n(g_csr_in,  si0, si1, g_xf, half, l16, af8);
    gather_dir_2n(g_csr_out, so0, so1, g_xr, half, l16, ar8);

    float4 sf = combine_halves(af8, half);
    float4 sr = combine_halves(ar8, half);

    float4 af = *(const float4*)(g_aggf + (size_t)n * D + colb);
    float4 ar = *(const float4*)(g_aggr + (size_t)n * D + colb);
    float4 s;
    s.x = af.x + sf.x * ci + ar.x + sr.x * co;
    s.y = af.y + sf.y * ci + ar.y + sr.y * co;
    s.z = af.z + sf.z * ci + ar.z + sr.z * co;
    s.w = af.w + sf.w * ci + ar.w + sr.w * co;

    float sum = s.x + s.y + s.z + s.w;
    #pragma unroll
    for (int o = 16; o; o >>= 1) sum += __shfl_xor_sync(0xffffffffu, sum, o);
    float mu = sum * (1.0f / 128.0f);

    float dx = s.x - mu, dy = s.y - mu, dz = s.z - mu, dw = s.w - mu;
    float sq = dx * dx + dy * dy + dz * dz + dw * dw;
    #pragma unroll
    for (int o = 16; o; o >>= 1) sq += __shfl_xor_sync(0xffffffffu, sq, o);
    float rs = rsqrtf(sq * (1.0f / 128.0f) + 1e-5f);

    float4 gg = *(const float4*)(lng + colb);
    float4 bb = *(const float4*)(lnb + colb);
    float4 y;
    y.x = lrelu(dx * rs * gg.x + bb.x);
    y.y = lrelu(dy * rs * gg.y + bb.y);
    y.z = lrelu(dz * rs * gg.z + bb.z);
    y.w = lrelu(dw * rs * gg.w + bb.w);

    float4 h = *(const float4*)(g_h + (size_t)n * D + colb);
    h.x += y.x; h.y += y.y; h.z += y.z; h.w += y.w;
    *(float4*)(g_h + (size_t)n * D + colb) = h;

    if (n >= NI) {
        *(float4*)(out + (size_t)(n - NI) * 512 + (size_t)(l + 1) * 128 + colb) = h;
    }
}

// ---------------- launch ----------------
extern "C" void kernel_launch(void* const* d_in, const int* in_sizes, int n_in,
                              void* d_out, int out_size)
{
    const float* x      = (const float*)d_in[0];
    const float* xnet   = (const float*)d_in[1];
    const float* encW1  = (const float*)d_in[2];
    const float* encb1  = (const float*)d_in[3];
    const float* encW2  = (const float*)d_in[4];
    const float* encb2  = (const float*)d_in[5];
    const float* encnW1 = (const float*)d_in[6];
    const float* encnb1 = (const float*)d_in[7];
    const float* encnW2 = (const float*)d_in[8];
    const float* encnb2 = (const float*)d_in[9];
    const float* convW  = (const float*)d_in[10];
    const float* convb  = (const float*)d_in[11];
    const float* convr  = (const float*)d_in[12];
    const float* rconvW = (const float*)d_in[13];
    const float* rconvb = (const float*)d_in[14];
    const float* rconvr = (const float*)d_in[15];
    const float* lng    = (const float*)d_in[16];
    const float* lnb    = (const float*)d_in[17];
    const int*   src    = (const int*)d_in[18];
    const int*   dst    = (const int*)d_in[19];

    int NI = in_sizes[0] / 11;
    int NN = in_sizes[1] / 3;
    int N  = NI + NN;
    int E  = in_sizes[18];
    float* out = (float*)d_out;

    size_t sm1 = (size_t)(11 * 256 + 256 + 128 * 260 + 128 + 64 * 12 + 64 * 256) * 4;
    cudaFuncSetAttribute(enc_kernel, cudaFuncAttributeMaxDynamicSharedMemorySize, (int)sm1);
    cudaFuncSetAttribute(conv_mma_kernel, cudaFuncAttributeMaxDynamicSharedMemorySize, SMEM_MMA);

    enc_kernel<<<148, 512, sm1>>>(x, xnet, encW1, encb1, encW2, encb2,
                                  encnW1, encnb1, encnW2, encnb2, NI, NN, N, out);
    deg_count_kernel<<<(E + 255) / 256, 256>>>(src, dst, E);
    scan_fin_kernel<<<2, 1024>>>(N, E);
    conv_mma_kernel<<<148, 512, SMEM_MMA>>>(convW, convb, convr, rconvW, rconvb, rconvr, N);
    fill_kernel<<<(E + 255) / 256, 256>>>(src, dst, E);

    int node_threads = N * 32;
    gather_post_kernel<<<(node_threads + 255) / 256, 256>>>(lng, lnb, out, NI, N, 0);

    for (int l = 1; l < 3; l++) {
        conv_mma_kernel<<<148, 512, SMEM_MMA>>>(convW + (size_t)l * 16384, convb + l * 128, convr + l * 128,
                                                rconvW + (size_t)l * 16384, rconvb + l * 128, rconvr + l * 128, N);
        gather_post_kernel<<<(node_threads + 255) / 256, 256>>>(lng + l * 128, lnb + l * 128, out, NI, N, l);
    }
}

// round 14
// speedup vs baseline: 1.0421x; 1.0037x over previous
#include <cuda_runtime.h>
#include <cuda_fp16.h>
#include <cstdint>

#define D 128
#define NMAX 50176
#define EMAX 1048576

typedef unsigned long long ull;

// ---------------- scratch ----------------
static __device__ float g_h[NMAX * D];
static __device__ __align__(16) __half g_xf[NMAX * D];   // dinv_in*relu(xf), fp16
static __device__ __align__(16) __half g_xr[NMAX * D];   // dinv_out*relu(xr), fp16
static __device__ float g_aggf[NMAX * D];
static __device__ float g_aggr[NMAX * D];
static __device__ float g_deg_in[NMAX];
static __device__ float g_deg_out[NMAX];
static __device__ float g_dinv_in[NMAX];
static __device__ float g_dinv_out[NMAX];
static __device__ float g_rdeg_in[NMAX];
static __device__ float g_rdeg_out[NMAX];
static __device__ int g_off_in[NMAX + 1];
static __device__ int g_off_out[NMAX + 1];
static __device__ int g_fill_in[NMAX];
static __device__ int g_fill_out[NMAX];
static __device__ int g_csr_in[EMAX];
static __device__ int g_csr_out[EMAX];

__device__ __forceinline__ float lrelu(float v) { return v >= 0.f ? v : 0.1f * v; }
__device__ __forceinline__ float4 lrelu4(float4 v) {
    return make_float4(lrelu(v.x), lrelu(v.y), lrelu(v.z), lrelu(v.w));
}
__device__ __forceinline__ void fma2(ull& d, ull a, ull b) {
    asm("fma.rn.f32x2 %0, %1, %2, %0;" : "+l"(d) : "l"(a), "l"(b));
}
__device__ __forceinline__ float unpack_sum(ull v) {
    float2 p = *(float2*)&v;
    return p.x + p.y;
}

// ---------------- mma.sync helpers ----------------
__device__ __forceinline__ uint32_t smem_u32(const void* p) {
    uint32_t a;
    asm("{ .reg .u64 t; cvta.to.shared.u64 t, %1; cvt.u32.u64 %0, t; }" : "=r"(a) : "l"(p));
    return a;
}
__device__ __forceinline__ void ldsm4(uint32_t* r, uint32_t addr) {
    asm volatile("ldmatrix.sync.aligned.m8n8.x4.shared.b16 {%0,%1,%2,%3}, [%4];"
                 : "=r"(r[0]), "=r"(r[1]), "=r"(r[2]), "=r"(r[3]) : "r"(addr));
}
__device__ __forceinline__ void mma16816(float* c, const uint32_t* a, uint32_t b0, uint32_t b1) {
    asm volatile("mma.sync.aligned.m16n8k16.row.col.f32.f16.f16.f32 "
                 "{%0,%1,%2,%3}, {%4,%5,%6,%7}, {%8,%9}, {%0,%1,%2,%3};"
                 : "+f"(c[0]), "+f"(c[1]), "+f"(c[2]), "+f"(c[3])
                 : "r"(a[0]), "r"(a[1]), "r"(a[2]), "r"(a[3]), "r"(b0), "r"(b1));
}

#define NETB 16

// ---------------- fused encoders (+ degree init) ----------------
__global__ void __launch_bounds__(512, 1)
enc_kernel(const float* __restrict__ x, const float* __restrict__ xn,
           const float* __restrict__ W1, const float* __restrict__ b1,
           const float* __restrict__ W2, const float* __restrict__ b2,
           const float* __restrict__ nW1, const float* __restrict__ nb1,
           const float* __restrict__ nW2, const float* __restrict__ nb2,
           int NI, int NN, int N, float* __restrict__ out)
{
    for (int i = blockIdx.x * 512 + threadIdx.x; i < N; i += gridDim.x * 512) {
        g_deg_in[i] = 1.0f; g_deg_out[i] = 1.0f;
    }

    extern __shared__ float sm[];
    int tid = threadIdx.x;

    if (blockIdx.x < NETB) {
        // ---- net path: 3 -> 128 -> 128 ----
        float* sW1  = sm;
        float* sb1  = sW1 + 128 * 3;
        float* sW2  = sb1 + 128;          // [c][k] stride 132
        float* sb2  = sW2 + 128 * 132;
        float* sX   = sb2 + 128;
        float* st   = sX + 64 * 4;

        for (int i = tid; i < 128 * 3; i += 512) sW1[i] = nW1[i];
        if (tid < 128) sb1[tid] = nb1[tid];
        for (int i = tid; i < 128 * 128; i += 512) {
            int c = i >> 7, k = i & 127;
            sW2[c * 132 + k] = nW2[i];
        }
        if (tid < 128) sb2[tid] = nb2[tid];
        __syncthreads();

        int rg2 = tid >> 5;
        int cg  = tid & 31;

        int numTiles = (NN + 63) / 64;
        for (int tile = blockIdx.x; tile < numTiles; tile += NETB) {
            int base = tile * 64;
            __syncthreads();
            for (int i = tid; i < 64 * 3; i += 512) {
                int r = i / 3, p = i % 3;
                int row = base + r;
                sX[r * 4 + p] = (row < NN) ? xn[(size_t)row * 3 + p] : 0.f;
            }
            __syncthreads();
            for (int i = tid; i < 64 * 128; i += 512) {
                int r = i >> 7, j = i & 127;
                float a = sb1[j] + sX[r * 4] * sW1[j * 3] + sX[r * 4 + 1] * sW1[j * 3 + 1]
                        + sX[r * 4 + 2] * sW1[j * 3 + 2];
                st[i] = lrelu(a);
            }
            __syncthreads();

            ull acc[4][4];
            #pragma unroll
            for (int r = 0; r < 4; r++)
                #pragma unroll
                for (int j = 0; j < 4; j++) acc[r][j] = 0ull;

            const float* tb = st + rg2 * 4 * 128;
            #pragma unroll 2
            for (int k = 0; k < 128; k += 4) {
                ull w01[4], w23[4];
                #pragma unroll
                for (int j = 0; j < 4; j++) {
                    float4 w = *(const float4*)(sW2 + (cg + 32 * j) * 132 + k);
                    w01[j] = ((ull*)&w)[0]; w23[j] = ((ull*)&w)[1];
                }
                #pragma unroll
                for (int r = 0; r < 4; r++) {
                    float4 h4 = *(const float4*)(tb + r * 128 + k);
                    ull h01 = ((ull*)&h4)[0], h23 = ((ull*)&h4)[1];
                    #pragma unroll
                    for (int j = 0; j < 4; j++) {
                        fma2(acc[r][j], h01, w01[j]);
                        fma2(acc[r][j], h23, w23[j]);
                    }
                }
            }
            #pragma unroll
            for (int r = 0; r < 4; r++) {
                int row = base + rg2 * 4 + r;
                if (row < NN) {
                    #pragma unroll
                    for (int j = 0; j < 4; j++) {
                        int c = cg + 32 * j;
                        float v = lrelu(unpack_sum(acc[r][j]) + sb2[c]);
                        g_h[(size_t)(NI + row) * D + c] = v;
                        out[(size_t)row * 512 + c] = v;
                    }
                }
            }
        }
    } else {
        // ---- instance path: 11 -> 256 -> 128 ----
        float* sW1T = sm;
        float* sb1  = sW1T + 11 * 256;
        float* sW2  = sb1 + 256;          // [c][k] stride 260
        float* sb2  = sW2 + 128 * 260;
        float* sX   = sb2 + 128;
        float* st   = sX + 64 * 12;

        for (int i = tid; i < 256 * 11; i += 512) {
            int j = i / 11, p = i % 11;
            sW1T[p * 256 + j] = W1[i];
        }
        if (tid < 256) sb1[tid] = b1[tid];
        for (int i = tid; i < 128 * 256; i += 512) {
            int c = i >> 8, k = i & 255;
            sW2[c * 260 + k] = W2[i];
        }
        if (tid < 128) sb2[tid] = b2[tid];
        __syncthreads();

        int rg1 = tid >> 6;
        int jg  = tid & 63;
        float4 b1v = *(const float4*)(sb1 + jg * 4);

        int rg2 = tid >> 5;
        int cg  = tid & 31;

        int nb = gridDim.x - NETB;
        int numTiles = (NI + 63) / 64;
        for (int tile = blockIdx.x - NETB; tile < numTiles; tile += nb) {
            int base = tile * 64;
            __syncthreads();
            for (int i = tid; i < 64 * 11; i += 512) {
                int r = i / 11, p = i % 11;
                int row = base + r;
                sX[r * 12 + p] = (row < NI) ? x[(size_t)row * 11 + p] : 0.f;
            }
            __syncthreads();

            {
                float4 acc[8];
                #pragma unroll
                for (int r = 0; r < 8; r++) acc[r] = b1v;
                #pragma unroll
                for (int p = 0; p < 11; p++) {
                    float4 w = *(const float4*)(sW1T + p * 256 + jg * 4);
                    #pragma unroll
                    for (int r = 0; r < 8; r++) {
                        float xv = sX[(rg1 * 8 + r) * 12 + p];
                        acc[r].x += xv * w.x; acc[r].y += xv * w.y;
                        acc[r].z += xv * w.z; acc[r].w += xv * w.w;
                    }
                }
                #pragma unroll
                for (int r = 0; r < 8; r++)
                    *(float4*)(st + (rg1 * 8 + r) * 256 + jg * 4) = lrelu4(acc[r]);
            }
            __syncthreads();

            {
                ull acc[4][4];
                #pragma unroll
                for (int r = 0; r < 4; r++)
                    #pragma unroll
                    for (int j = 0; j < 4; j++) acc[r][j] = 0ull;

                const float* tb = st + rg2 * 4 * 256;
                #pragma unroll 2
                for (int k = 0; k < 256; k += 4) {
                    ull w01[4], w23[4];
                    #pragma unroll
                    for (int j = 0; j < 4; j++) {
                        float4 w = *(const float4*)(sW2 + (cg + 32 * j) * 260 + k);
                        w01[j] = ((ull*)&w)[0]; w23[j] = ((ull*)&w)[1];
                    }
                    #pragma unroll
                    for (int r = 0; r < 4; r++) {
                        float4 h4 = *(const float4*)(tb + r * 256 + k);
                        ull h01 = ((ull*)&h4)[0], h23 = ((ull*)&h4)[1];
                        #pragma unroll
                        for (int j = 0; j < 4; j++) {
                            fma2(acc[r][j], h01, w01[j]);
                            fma2(acc[r][j], h23, w23[j]);
                        }
                    }
                }
                #pragma unroll
                for (int r = 0; r < 4; r++) {
                    int row = base + rg2 * 4 + r;
                    if (row < NI) {
                        #pragma unroll
                        for (int j = 0; j < 4; j++) {
                            int c = cg + 32 * j;
                            float v = lrelu(unpack_sum(acc[r][j]) + sb2[c]);
                            g_h[(size_t)row * D + c] = v;
                        }
                    }
                }
            }
        }
    }
}

// ---------------- degree count ----------------
__global__ void deg_count_kernel(const int* __restrict__ src, const int* __restrict__ dst, int E)
{
    int e = blockIdx.x * blockDim.x + threadIdx.x;
    if (e < E) {
        atomicAdd(&g_deg_in[dst[e]], 1.0f);
        atomicAdd(&g_deg_out[src[e]], 1.0f);
    }
}

// ---------------- scan + fin ----------------
__global__ void scan_fin_kernel(int N, int E)
{
    __shared__ int warp_sums[32];
    __shared__ int warp_offs[32];
    __shared__ int chunk_tot;
    __shared__ int carry_s;
    const float* deg = (blockIdx.x == 0) ? g_deg_in : g_deg_out;
    int* off = (blockIdx.x == 0) ? g_off_in : g_off_out;
    int tid = threadIdx.x, lane = tid & 31, wid = tid >> 5;
    if (tid == 0) carry_s = 0;
    __syncthreads();
    for (int base = 0; base < N; base += 1024) {
        int i = base + tid;
        int v = (i < N) ? ((int)deg[i]) - 1 : 0;
        int incl = v;
        #pragma unroll
        for (int o = 1; o < 32; o <<= 1) {
            int t = __shfl_up_sync(0xffffffffu, incl, o);
            if (lane >= o) incl += t;
        }
        if (lane == 31) warp_sums[wid] = incl;
        __syncthreads();
        if (wid == 0) {
            int ws = warp_sums[lane];
            int wi = ws;
            #pragma unroll
            for (int o = 1; o < 32; o <<= 1) {
                int t = __shfl_up_sync(0xffffffffu, wi, o);
                if (lane >= o) wi += t;
            }
            warp_offs[lane] = wi - ws;
            if (lane == 31) chunk_tot = wi;
        }
        __syncthreads();
        if (i < N) off[i] = carry_s + warp_offs[wid] + incl - v;
        __syncthreads();
        if (tid == 0) carry_s += chunk_tot;
    }
    if (tid == 0) off[N] = E;
    if (blockIdx.x == 0) {
        for (int i = tid; i < N; i += 1024) {
            float a = g_deg_in[i];
            g_dinv_in[i] = rsqrtf(a);
            g_rdeg_in[i] = 1.0f / a;
            g_fill_in[i] = 0;
        }
    } else {
        for (int i = tid; i < N; i += 1024) {
            float a = g_deg_out[i];
            g_dinv_out[i] = rsqrtf(a);
            g_rdeg_out[i] = 1.0f / a;
            g_fill_out[i] = 0;
        }
    }
}

__global__ void fill_kernel(const int* __restrict__ src, const int* __restrict__ dst, int E)
{
    int e = blockIdx.x * blockDim.x + threadIdx.x;
    if (e < E) {
        int s = src[e], d = dst[e];
        int p = atomicAdd(&g_fill_in[d], 1);
        g_csr_in[g_off_in[d] + p] = s;
        int q = atomicAdd(&g_fill_out[s], 1);
        g_csr_out[g_off_out[s] + q] = d;
    }
}

// ---------------- per-layer dense part: mma.sync 2-term split, one direction per CTA ----------------
// grid 296 (rev = bid&1); smem = W_hi + W_lo + A_hi = ~104KB -> 2 CTAs/SM = 32 warps.
// 16 warps: rg = w>>1 (16-row group), ch = w&1 (64-col half). acc[8][4] = 32 regs.
#define PH 136       // smem pitch in halves
#define PB 272       // smem pitch in bytes
#define TILE_B (128 * PB)          // 34816
#define OFF_W_HI 0
#define OFF_W_LO (1 * TILE_B)
#define OFF_A_HI (2 * TILE_B)
#define OFF_BIAS (3 * TILE_B)      // float[128]
#define OFF_ROOT (3 * TILE_B + 512)
#define SMEM_MMA (3 * TILE_B + 1024)   // 105472

__global__ void __launch_bounds__(512, 2)
conv_mma_kernel(const float* __restrict__ Wf, const float* __restrict__ bf,
                const float* __restrict__ rootf,
                const float* __restrict__ Wr, const float* __restrict__ br,
                const float* __restrict__ rootr, int N)
{
    extern __shared__ __align__(16) char smc[];
    uint32_t sbase = smem_u32(smc);
    int tid = threadIdx.x;
    int dir = blockIdx.x & 1;

    const float* Wg = dir ? Wr : Wf;
    const float* bg = dir ? br : bf;
    const float* rg_g = dir ? rootr : rootf;

    float* sbias = (float*)(smc + OFF_BIAS);
    float* sroot = (float*)(smc + OFF_ROOT);
    if (tid < 128) { sbias[tid] = bg[tid]; sroot[tid] = rg_g[tid]; }

    for (int i = tid; i < 128 * 64; i += 512) {
        int c = i >> 6, k2 = (i & 63) << 1;
        int ho = c * PH + k2;
        float2 wv = *(const float2*)(Wg + c * 128 + k2);
        half2 hv = __float22half2_rn(wv);
        float2 bk = __half22float2(hv);
        *(half2*)((__half*)(smc + OFF_W_HI) + ho) = hv;
        *(half2*)((__half*)(smc + OFF_W_LO) + ho) =
            __float22half2_rn(make_float2(wv.x - bk.x, wv.y - bk.y));
    }
    __syncthreads();

    int w = tid >> 5, lane = tid & 31;
    int rg = w >> 1;          // 0..7: 16-row group
    int ch = w & 1;           // 0/1: 64-col half
    int wm = rg * 16;

    uint32_t aLaneOff = (uint32_t)((wm + (lane & 15)) * PB + ((lane >> 4) << 4));
    uint32_t bLaneOff = (uint32_t)(((((lane >> 4) << 3) + (lane & 7)) * PB) + ((((lane >> 3) & 1)) << 4));
    uint32_t aHiAddr = sbase + OFF_A_HI + aLaneOff;
    uint32_t bHiAddr = sbase + OFF_W_HI + (uint32_t)(ch * 64 * PB) + bLaneOff;
    uint32_t bLoAddr = sbase + OFF_W_LO + (uint32_t)(ch * 64 * PB) + bLaneOff;

    __half* xout = dir ? g_xr : g_xf;
    float* aout = dir ? g_aggr : g_aggf;
    const float* rdegp = dir ? g_rdeg_out : g_rdeg_in;
    const float* dinvp = dir ? g_dinv_out : g_dinv_in;

    int numTiles = (N + 127) / 128;
    int step = gridDim.x >> 1;
    for (int tile = blockIdx.x >> 1; tile < numTiles; tile += step) {
        int base = tile * 128;
        __syncthreads();
        for (int i = tid; i < 128 * 64; i += 512) {
            int r = i >> 6, k2 = (i & 63) << 1;
            int row = base + r;
            float2 v = (row < N) ? *(const float2*)(g_h + (size_t)row * D + k2)
                                 : make_float2(0.f, 0.f);
            *(half2*)((__half*)(smc + OFF_A_HI) + r * PH + k2) = __float22half2_rn(v);
        }
        __syncthreads();

        float acc[8][4];
        #pragma unroll
        for (int nf = 0; nf < 8; nf++)
            #pragma unroll
            for (int j = 0; j < 4; j++) acc[nf][j] = 0.f;

        #pragma unroll 1
        for (int kf = 0; kf < 8; kf++) {
            uint32_t ko = kf * 32;
            uint32_t ah[4];
            ldsm4(ah, aHiAddr + ko);
            #pragma unroll
            for (int nb = 0; nb < 4; nb++) {
                uint32_t boff = (uint32_t)(nb * 16 * PB) + ko;
                uint32_t bh[4], bl[4];
                ldsm4(bh, bHiAddr + boff);
                ldsm4(bl, bLoAddr + boff);
                mma16816(acc[nb * 2],     ah, bh[0], bh[1]);
                mma16816(acc[nb * 2],     ah, bl[0], bl[1]);
                mma16816(acc[nb * 2 + 1], ah, bh[2], bh[3]);
                mma16816(acc[nb * 2 + 1], ah, bl[2], bl[3]);
            }
        }

        int g = lane >> 2, t4 = lane & 3;
        int row0 = base + wm + g;
        int row1 = row0 + 8;
        float di0 = 0.f, rd0 = 0.f, di1 = 0.f, rd1 = 0.f;
        if (row0 < N) { di0 = dinvp[row0]; rd0 = rdegp[row0]; }
        if (row1 < N) { di1 = dinvp[row1]; rd1 = rdegp[row1]; }
        #pragma unroll
        for (int nf = 0; nf < 8; nf++) {
            int col = ch * 64 + nf * 8 + t4 * 2;
            float2 bb = *(const float2*)(sbias + col);
            float2 rr = *(const float2*)(sroot + col);
            if (row0 < N) {
                float v0 = acc[nf][0] + bb.x, v1 = acc[nf][1] + bb.y;
                half2 xh = __floats2half2_rn(fmaxf(v0, 0.f) * di0, fmaxf(v1, 0.f) * di0);
                *(half2*)(xout + (size_t)row0 * D + col) = xh;
                *(float2*)(aout + (size_t)row0 * D + col) =
                    make_float2(fmaxf(v0 + rr.x, 0.f) * rd0, fmaxf(v1 + rr.y, 0.f) * rd0);
            }
            if (row1 < N) {
                float v2 = acc[nf][2] + bb.x, v3 = acc[nf][3] + bb.y;
                half2 xh = __floats2half2_rn(fmaxf(v2, 0.f) * di1, fmaxf(v3, 0.f) * di1);
                *(half2*)(xout + (size_t)row1 * D + col) = xh;
                *(float2*)(aout + (size_t)row1 * D + col) =
                    make_float2(fmaxf(v2 + rr.x, 0.f) * rd1, fmaxf(v3 + rr.y, 0.f) * rd1);
            }
        }
    }
}

// ---------------- fused gather (R11 version: 1 warp/node, 2 neighbors/iter) ----------------
__device__ __forceinline__ void gather_dir_2n(const int* __restrict__ csr, int s0, int s1,
                                              const __half* __restrict__ xs,
                                              int half, int l16, float* acc8)
{
    for (int j = s0; j < s1; j += 32) {
        int nn = s1 - j; if (nn > 32) nn = 32;
        int lane = half * 16 + l16;
        int idx = (lane < nn) ? csr[j + lane] : 0;
        if (nn == 32) {
            #pragma unroll
            for (int k = 0; k < 16; k++) {
                int id = __shfl_sync(0xffffffffu, idx, 2 * k + half);
                uint4 v = *(const uint4*)(xs + (size_t)id * D + l16 * 8);
                float2 f0 = __half22float2(*(half2*)&v.x);
                float2 f1 = __half22float2(*(half2*)&v.y);
                float2 f2 = __half22float2(*(half2*)&v.z);
                float2 f3 = __half22float2(*(half2*)&v.w);
                acc8[0] += f0.x; acc8[1] += f0.y; acc8[2] += f1.x; acc8[3] += f1.y;
                acc8[4] += f2.x; acc8[5] += f2.y; acc8[6] += f3.x; acc8[7] += f3.y;
            }
        } else {
            int pairs = (nn + 1) >> 1;
            for (int k = 0; k < pairs; k++) {
                int slot = 2 * k + half;
                int id = __shfl_sync(0xffffffffu, idx, slot < nn ? slot : 0);
                if (slot < nn) {
                    uint4 v = *(const uint4*)(xs + (size_t)id * D + l16 * 8);
                    float2 f0 = __half22float2(*(half2*)&v.x);
                    float2 f1 = __half22float2(*(half2*)&v.y);
                    float2 f2 = __half22float2(*(half2*)&v.z);
                    float2 f3 = __half22float2(*(half2*)&v.w);
                    acc8[0] += f0.x; acc8[1] += f0.y; acc8[2] += f1.x; acc8[3] += f1.y;
                    acc8[4] += f2.x; acc8[5] += f2.y; acc8[6] += f3.x; acc8[7] += f3.y;
                }
            }
        }
    }
}

__device__ __forceinline__ float4 combine_halves(const float* acc8, int half)
{
    float r[4];
    #pragma unroll
    for (int m = 0; m < 4; m++) {
        float send = half ? acc8[m] : acc8[4 + m];
        float recv = __shfl_xor_sync(0xffffffffu, send, 16);
        float keep = half ? acc8[4 + m] : acc8[m];
        r[m] = keep + recv;
    }
    return make_float4(r[0], r[1], r[2], r[3]);
}

__global__ void gather_post_kernel(const float* __restrict__ lng, const float* __restrict__ lnb,
                                   float* __restrict__ out, int NI, int N, int l)
{
    int gt = blockIdx.x * blockDim.x + threadIdx.x;
    int n = gt >> 5, lane = gt & 31;
    if (n >= N) return;
    int half = lane >> 4, l16 = lane & 15;
    int colb = l16 * 8 + half * 4;

    int si0 = g_off_in[n],  si1 = g_off_in[n + 1];
    int so0 = g_off_out[n], so1 = g_off_out[n + 1];
    float ci = g_dinv_in[n], co = g_dinv_out[n];

    float af8[8], ar8[8];
    #pragma unroll
    for (int j = 0; j < 8; j++) { af8[j] = 0.f; ar8[j] = 0.f; }

    gather_dir_2n(g_csr_in,  si0, si1, g_xf, half, l16, af8);
    gather_dir_2n(g_csr_out, so0, so1, g_xr, half, l16, ar8);

    float4 sf = combine_halves(af8, half);
    float4 sr = combine_halves(ar8, half);

    float4 af = *(const float4*)(g_aggf + (size_t)n * D + colb);
    float4 ar = *(const float4*)(g_aggr + (size_t)n * D + colb);
    float4 s;
    s.x = af.x + sf.x * ci + ar.x + sr.x * co;
    s.y = af.y + sf.y * ci + ar.y + sr.y * co;
    s.z = af.z + sf.z * ci + ar.z + sr.z * co;
    s.w = af.w + sf.w * ci + ar.w + sr.w * co;

    float sum = s.x + s.y + s.z + s.w;
    #pragma unroll
    for (int o = 16; o; o >>= 1) sum += __shfl_xor_sync(0xffffffffu, sum, o);
    float mu = sum * (1.0f / 128.0f);

    float dx = s.x - mu, dy = s.y - mu, dz = s.z - mu, dw = s.w - mu;
    float sq = dx * dx + dy * dy + dz * dz + dw * dw;
    #pragma unroll
    for (int o = 16; o; o >>= 1) sq += __shfl_xor_sync(0xffffffffu, sq, o);
    float rs = rsqrtf(sq * (1.0f / 128.0f) + 1e-5f);

    float4 gg = *(const float4*)(lng + colb);
    float4 bb = *(const float4*)(lnb + colb);
    float4 y;
    y.x = lrelu(dx * rs * gg.x + bb.x);
    y.y = lrelu(dy * rs * gg.y + bb.y);
    y.z = lrelu(dz * rs * gg.z + bb.z);
    y.w = lrelu(dw * rs * gg.w + bb.w);

    float4 h = *(const float4*)(g_h + (size_t)n * D + colb);
    h.x += y.x; h.y += y.y; h.z += y.z; h.w += y.w;
    *(float4*)(g_h + (size_t)n * D + colb) = h;

    if (n >= NI) {
        *(float4*)(out + (size_t)(n - NI) * 512 + (size_t)(l + 1) * 128 + colb) = h;
    }
}

// ---------------- launch ----------------
extern "C" void kernel_launch(void* const* d_in, const int* in_sizes, int n_in,
                              void* d_out, int out_size)
{
    const float* x      = (const float*)d_in[0];
    const float* xnet   = (const float*)d_in[1];
    const float* encW1  = (const float*)d_in[2];
    const float* encb1  = (const float*)d_in[3];
    const float* encW2  = (const float*)d_in[4];
    const float* encb2  = (const float*)d_in[5];
    const float* encnW1 = (const float*)d_in[6];
    const float* encnb1 = (const float*)d_in[7];
    const float* encnW2 = (const float*)d_in[8];
    const float* encnb2 = (const float*)d_in[9];
    const float* convW  = (const float*)d_in[10];
    const float* convb  = (const float*)d_in[11];
    const float* convr  = (const float*)d_in[12];
    const float* rconvW = (const float*)d_in[13];
    const float* rconvb = (const float*)d_in[14];
    const float* rconvr = (const float*)d_in[15];
    const float* lng    = (const float*)d_in[16];
    const float* lnb    = (const float*)d_in[17];
    const int*   src    = (const int*)d_in[18];
    const int*   dst    = (const int*)d_in[19];

    int NI = in_sizes[0] / 11;
    int NN = in_sizes[1] / 3;
    int N  = NI + NN;
    int E  = in_sizes[18];
    float* out = (float*)d_out;

    size_t sm1 = (size_t)(11 * 256 + 256 + 128 * 260 + 128 + 64 * 12 + 64 * 256) * 4;
    cudaFuncSetAttribute(enc_kernel, cudaFuncAttributeMaxDynamicSharedMemorySize, (int)sm1);
    cudaFuncSetAttribute(conv_mma_kernel, cudaFuncAttributeMaxDynamicSharedMemorySize, SMEM_MMA);

    enc_kernel<<<148, 512, sm1>>>(x, xnet, encW1, encb1, encW2, encb2,
                                  encnW1, encnb1, encnW2, encnb2, NI, NN, N, out);
    deg_count_kernel<<<(E + 255) / 256, 256>>>(src, dst, E);
    scan_fin_kernel<<<2, 1024>>>(N, E);
    conv_mma_kernel<<<296, 512, SMEM_MMA>>>(convW, convb, convr, rconvW, rconvb, rconvr, N);
    fill_kernel<<<(E + 255) / 256, 256>>>(src, dst, E);

    int node_threads = N * 32;
    gather_post_kernel<<<(node_threads + 255) / 256, 256>>>(lng, lnb, out, NI, N, 0);

    for (int l = 1; l < 3; l++) {
        conv_mma_kernel<<<296, 512, SMEM_MMA>>>(convW + (size_t)l * 16384, convb + l * 128, convr + l * 128,
                                                rconvW + (size_t)l * 16384, rconvb + l * 128, rconvr + l * 128, N);
        gather_post_kernel<<<(node_threads + 255) / 256, 256>>>(lng + l * 128, lnb + l * 128, out, NI, N, l);
    }
}

// round 15
// speedup vs baseline: 1.0820x; 1.0383x over previous
#include <cuda_runtime.h>
#include <cuda_fp16.h>
#include <cstdint>

#define D 128
#define NMAX 50176
#define EMAX 1048576

typedef unsigned long long ull;

// ---------------- scratch ----------------
static __device__ float g_h[NMAX * D];
static __device__ __align__(16) __half g_xf[NMAX * D];   // dinv_in*relu(xf), fp16
static __device__ __align__(16) __half g_xr[NMAX * D];   // dinv_out*relu(xr), fp16
static __device__ __align__(16) __half g_aggf[NMAX * D]; // self-loop term, fp16
static __device__ __align__(16) __half g_aggr[NMAX * D];
static __device__ float g_deg_in[NMAX];
static __device__ float g_deg_out[NMAX];
static __device__ float g_dinv_in[NMAX];
static __device__ float g_dinv_out[NMAX];
static __device__ float g_rdeg_in[NMAX];
static __device__ float g_rdeg_out[NMAX];
static __device__ int g_off_in[NMAX + 1];
static __device__ int g_off_out[NMAX + 1];
static __device__ int g_fill_in[NMAX];
static __device__ int g_fill_out[NMAX];
static __device__ int g_csr_in[EMAX];
static __device__ int g_csr_out[EMAX];

__device__ __forceinline__ float lrelu(float v) { return v >= 0.f ? v : 0.1f * v; }
__device__ __forceinline__ float4 lrelu4(float4 v) {
    return make_float4(lrelu(v.x), lrelu(v.y), lrelu(v.z), lrelu(v.w));
}
__device__ __forceinline__ void fma2(ull& d, ull a, ull b) {
    asm("fma.rn.f32x2 %0, %1, %2, %0;" : "+l"(d) : "l"(a), "l"(b));
}
__device__ __forceinline__ float unpack_sum(ull v) {
    float2 p = *(float2*)&v;
    return p.x + p.y;
}

// ---------------- mma.sync helpers ----------------
__device__ __forceinline__ uint32_t smem_u32(const void* p) {
    uint32_t a;
    asm("{ .reg .u64 t; cvta.to.shared.u64 t, %1; cvt.u32.u64 %0, t; }" : "=r"(a) : "l"(p));
    return a;
}
__device__ __forceinline__ void ldsm4(uint32_t* r, uint32_t addr) {
    asm volatile("ldmatrix.sync.aligned.m8n8.x4.shared.b16 {%0,%1,%2,%3}, [%4];"
                 : "=r"(r[0]), "=r"(r[1]), "=r"(r[2]), "=r"(r[3]) : "r"(addr));
}
__device__ __forceinline__ void mma16816(float* c, const uint32_t* a, uint32_t b0, uint32_t b1) {
    asm volatile("mma.sync.aligned.m16n8k16.row.col.f32.f16.f16.f32 "
                 "{%0,%1,%2,%3}, {%4,%5,%6,%7}, {%8,%9}, {%0,%1,%2,%3};"
                 : "+f"(c[0]), "+f"(c[1]), "+f"(c[2]), "+f"(c[3])
                 : "r"(a[0]), "r"(a[1]), "r"(a[2]), "r"(a[3]), "r"(b0), "r"(b1));
}

#define NETB 16

// ---------------- fused encoders (+ degree init) ----------------
__global__ void __launch_bounds__(512, 1)
enc_kernel(const float* __restrict__ x, const float* __restrict__ xn,
           const float* __restrict__ W1, const float* __restrict__ b1,
           const float* __restrict__ W2, const float* __restrict__ b2,
           const float* __restrict__ nW1, const float* __restrict__ nb1,
           const float* __restrict__ nW2, const float* __restrict__ nb2,
           int NI, int NN, int N, float* __restrict__ out)
{
    for (int i = blockIdx.x * 512 + threadIdx.x; i < N; i += gridDim.x * 512) {
        g_deg_in[i] = 1.0f; g_deg_out[i] = 1.0f;
    }

    extern __shared__ float sm[];
    int tid = threadIdx.x;

    if (blockIdx.x < NETB) {
        // ---- net path: 3 -> 128 -> 128 ----
        float* sW1  = sm;
        float* sb1  = sW1 + 128 * 3;
        float* sW2  = sb1 + 128;          // [c][k] stride 132
        float* sb2  = sW2 + 128 * 132;
        float* sX   = sb2 + 128;
        float* st   = sX + 64 * 4;

        for (int i = tid; i < 128 * 3; i += 512) sW1[i] = nW1[i];
        if (tid < 128) sb1[tid] = nb1[tid];
        for (int i = tid; i < 128 * 128; i += 512) {
            int c = i >> 7, k = i & 127;
            sW2[c * 132 + k] = nW2[i];
        }
        if (tid < 128) sb2[tid] = nb2[tid];
        __syncthreads();

        int rg2 = tid >> 5;
        int cg  = tid & 31;

        int numTiles = (NN + 63) / 64;
        for (int tile = blockIdx.x; tile < numTiles; tile += NETB) {
            int base = tile * 64;
            __syncthreads();
            for (int i = tid; i < 64 * 3; i += 512) {
                int r = i / 3, p = i % 3;
                int row = base + r;
                sX[r * 4 + p] = (row < NN) ? xn[(size_t)row * 3 + p] : 0.f;
            }
            __syncthreads();
            for (int i = tid; i < 64 * 128; i += 512) {
                int r = i >> 7, j = i & 127;
                float a = sb1[j] + sX[r * 4] * sW1[j * 3] + sX[r * 4 + 1] * sW1[j * 3 + 1]
                        + sX[r * 4 + 2] * sW1[j * 3 + 2];
                st[i] = lrelu(a);
            }
            __syncthreads();

            ull acc[4][4];
            #pragma unroll
            for (int r = 0; r < 4; r++)
                #pragma unroll
                for (int j = 0; j < 4; j++) acc[r][j] = 0ull;

            const float* tb = st + rg2 * 4 * 128;
            #pragma unroll 2
            for (int k = 0; k < 128; k += 4) {
                ull w01[4], w23[4];
                #pragma unroll
                for (int j = 0; j < 4; j++) {
                    float4 w = *(const float4*)(sW2 + (cg + 32 * j) * 132 + k);
                    w01[j] = ((ull*)&w)[0]; w23[j] = ((ull*)&w)[1];
                }
                #pragma unroll
                for (int r = 0; r < 4; r++) {
                    float4 h4 = *(const float4*)(tb + r * 128 + k);
                    ull h01 = ((ull*)&h4)[0], h23 = ((ull*)&h4)[1];
                    #pragma unroll
                    for (int j = 0; j < 4; j++) {
                        fma2(acc[r][j], h01, w01[j]);
                        fma2(acc[r][j], h23, w23[j]);
                    }
                }
            }
            #pragma unroll
            for (int r = 0; r < 4; r++) {
                int row = base + rg2 * 4 + r;
                if (row < NN) {
                    #pragma unroll
                    for (int j = 0; j < 4; j++) {
                        int c = cg + 32 * j;
                        float v = lrelu(unpack_sum(acc[r][j]) + sb2[c]);
                        g_h[(size_t)(NI + row) * D + c] = v;
                        out[(size_t)row * 512 + c] = v;
                    }
                }
            }
        }
    } else {
        // ---- instance path: 11 -> 256 -> 128 ----
        float* sW1T = sm;
        float* sb1  = sW1T + 11 * 256;
        float* sW2  = sb1 + 256;          // [c][k] stride 260
        float* sb2  = sW2 + 128 * 260;
        float* sX   = sb2 + 128;
        float* st   = sX + 64 * 12;

        for (int i = tid; i < 256 * 11; i += 512) {
            int j = i / 11, p = i % 11;
            sW1T[p * 256 + j] = W1[i];
        }
        if (tid < 256) sb1[tid] = b1[tid];
        for (int i = tid; i < 128 * 256; i += 512) {
            int c = i >> 8, k = i & 255;
            sW2[c * 260 + k] = W2[i];
        }
        if (tid < 128) sb2[tid] = b2[tid];
        __syncthreads();

        int rg1 = tid >> 6;
        int jg  = tid & 63;
        float4 b1v = *(const float4*)(sb1 + jg * 4);

        int rg2 = tid >> 5;
        int cg  = tid & 31;

        int nb = gridDim.x - NETB;
        int numTiles = (NI + 63) / 64;
        for (int tile = blockIdx.x - NETB; tile < numTiles; tile += nb) {
            int base = tile * 64;
            __syncthreads();
            for (int i = tid; i < 64 * 11; i += 512) {
                int r = i / 11, p = i % 11;
                int row = base + r;
                sX[r * 12 + p] = (row < NI) ? x[(size_t)row * 11 + p] : 0.f;
            }
            __syncthreads();

            {
                float4 acc[8];
                #pragma unroll
                for (int r = 0; r < 8; r++) acc[r] = b1v;
                #pragma unroll
                for (int p = 0; p < 11; p++) {
                    float4 w = *(const float4*)(sW1T + p * 256 + jg * 4);
                    #pragma unroll
                    for (int r = 0; r < 8; r++) {
                        float xv = sX[(rg1 * 8 + r) * 12 + p];
                        acc[r].x += xv * w.x; acc[r].y += xv * w.y;
                        acc[r].z += xv * w.z; acc[r].w += xv * w.w;
                    }
                }
                #pragma unroll
                for (int r = 0; r < 8; r++)
                    *(float4*)(st + (rg1 * 8 + r) * 256 + jg * 4) = lrelu4(acc[r]);
            }
            __syncthreads();

            {
                ull acc[4][4];
                #pragma unroll
                for (int r = 0; r < 4; r++)
                    #pragma unroll
                    for (int j = 0; j < 4; j++) acc[r][j] = 0ull;

                const float* tb = st + rg2 * 4 * 256;
                #pragma unroll 2
                for (int k = 0; k < 256; k += 4) {
                    ull w01[4], w23[4];
                    #pragma unroll
                    for (int j = 0; j < 4; j++) {
                        float4 w = *(const float4*)(sW2 + (cg + 32 * j) * 260 + k);
                        w01[j] = ((ull*)&w)[0]; w23[j] = ((ull*)&w)[1];
                    }
                    #pragma unroll
                    for (int r = 0; r < 4; r++) {
                        float4 h4 = *(const float4*)(tb + r * 256 + k);
                        ull h01 = ((ull*)&h4)[0], h23 = ((ull*)&h4)[1];
                        #pragma unroll
                        for (int j = 0; j < 4; j++) {
                            fma2(acc[r][j], h01, w01[j]);
                            fma2(acc[r][j], h23, w23[j]);
                        }
                    }
                }
                #pragma unroll
                for (int r = 0; r < 4; r++) {
                    int row = base + rg2 * 4 + r;
                    if (row < NI) {
                        #pragma unroll
                        for (int j = 0; j < 4; j++) {
                            int c = cg + 32 * j;
                            float v = lrelu(unpack_sum(acc[r][j]) + sb2[c]);
                            g_h[(size_t)row * D + c] = v;
                        }
                    }
                }
            }
        }
    }
}

// ---------------- degree count ----------------
__global__ void deg_count_kernel(const int* __restrict__ src, const int* __restrict__ dst, int E)
{
    int e = blockIdx.x * blockDim.x + threadIdx.x;
    if (e < E) {
        atomicAdd(&g_deg_in[dst[e]], 1.0f);
        atomicAdd(&g_deg_out[src[e]], 1.0f);
    }
}

// ---------------- scan + fin ----------------
__global__ void scan_fin_kernel(int N, int E)
{
    __shared__ int warp_sums[32];
    __shared__ int warp_offs[32];
    __shared__ int chunk_tot;
    __shared__ int carry_s;
    const float* deg = (blockIdx.x == 0) ? g_deg_in : g_deg_out;
    int* off = (blockIdx.x == 0) ? g_off_in : g_off_out;
    int tid = threadIdx.x, lane = tid & 31, wid = tid >> 5;
    if (tid == 0) carry_s = 0;
    __syncthreads();
    for (int base = 0; base < N; base += 1024) {
        int i = base + tid;
        int v = (i < N) ? ((int)deg[i]) - 1 : 0;
        int incl = v;
        #pragma unroll
        for (int o = 1; o < 32; o <<= 1) {
            int t = __shfl_up_sync(0xffffffffu, incl, o);
            if (lane >= o) incl += t;
        }
        if (lane == 31) warp_sums[wid] = incl;
        __syncthreads();
        if (wid == 0) {
            int ws = warp_sums[lane];
            int wi = ws;
            #pragma unroll
            for (int o = 1; o < 32; o <<= 1) {
                int t = __shfl_up_sync(0xffffffffu, wi, o);
                if (lane >= o) wi += t;
            }
            warp_offs[lane] = wi - ws;
            if (lane == 31) chunk_tot = wi;
        }
        __syncthreads();
        if (i < N) off[i] = carry_s + warp_offs[wid] + incl - v;
        __syncthreads();
        if (tid == 0) carry_s += chunk_tot;
    }
    if (tid == 0) off[N] = E;
    if (blockIdx.x == 0) {
        for (int i = tid; i < N; i += 1024) {
            float a = g_deg_in[i];
            g_dinv_in[i] = rsqrtf(a);
            g_rdeg_in[i] = 1.0f / a;
            g_fill_in[i] = 0;
        }
    } else {
        for (int i = tid; i < N; i += 1024) {
            float a = g_deg_out[i];
            g_dinv_out[i] = rsqrtf(a);
            g_rdeg_out[i] = 1.0f / a;
            g_fill_out[i] = 0;
        }
    }
}

__global__ void fill_kernel(const int* __restrict__ src, const int* __restrict__ dst, int E)
{
    int e = blockIdx.x * blockDim.x + threadIdx.x;
    if (e < E) {
        int s = src[e], d = dst[e];
        int p = atomicAdd(&g_fill_in[d], 1);
        g_csr_in[g_off_in[d] + p] = s;
        int q = atomicAdd(&g_fill_out[s], 1);
        g_csr_out[g_off_out[s] + q] = d;
    }
}

// ---------------- per-layer dense part: mma.sync 2-term split, one direction per CTA ----------------
#define PH 136       // smem pitch in halves
#define PB 272       // smem pitch in bytes
#define TILE_B (128 * PB)          // 34816
#define OFF_W_HI 0
#define OFF_W_LO (1 * TILE_B)
#define OFF_A_HI (2 * TILE_B)
#define OFF_BIAS (3 * TILE_B)      // float[128]
#define OFF_ROOT (3 * TILE_B + 512)
#define SMEM_MMA (3 * TILE_B + 1024)   // 105472

__global__ void __launch_bounds__(512, 2)
conv_mma_kernel(const float* __restrict__ Wf, const float* __restrict__ bf,
                const float* __restrict__ rootf,
                const float* __restrict__ Wr, const float* __restrict__ br,
                const float* __restrict__ rootr, int N)
{
    extern __shared__ __align__(16) char smc[];
    uint32_t sbase = smem_u32(smc);
    int tid = threadIdx.x;
    int dir = blockIdx.x & 1;

    const float* Wg = dir ? Wr : Wf;
    const float* bg = dir ? br : bf;
    const float* rg_g = dir ? rootr : rootf;

    float* sbias = (float*)(smc + OFF_BIAS);
    float* sroot = (float*)(smc + OFF_ROOT);
    if (tid < 128) { sbias[tid] = bg[tid]; sroot[tid] = rg_g[tid]; }

    for (int i = tid; i < 128 * 64; i += 512) {
        int c = i >> 6, k2 = (i & 63) << 1;
        int ho = c * PH + k2;
        float2 wv = *(const float2*)(Wg + c * 128 + k2);
        half2 hv = __float22half2_rn(wv);
        float2 bk = __half22float2(hv);
        *(half2*)((__half*)(smc + OFF_W_HI) + ho) = hv;
        *(half2*)((__half*)(smc + OFF_W_LO) + ho) =
            __float22half2_rn(make_float2(wv.x - bk.x, wv.y - bk.y));
    }
    __syncthreads();

    int w = tid >> 5, lane = tid & 31;
    int rg = w >> 1;          // 0..7: 16-row group
    int ch = w & 1;           // 0/1: 64-col half
    int wm = rg * 16;

    uint32_t aLaneOff = (uint32_t)((wm + (lane & 15)) * PB + ((lane >> 4) << 4));
    uint32_t bLaneOff = (uint32_t)(((((lane >> 4) << 3) + (lane & 7)) * PB) + ((((lane >> 3) & 1)) << 4));
    uint32_t aHiAddr = sbase + OFF_A_HI + aLaneOff;
    uint32_t bHiAddr = sbase + OFF_W_HI + (uint32_t)(ch * 64 * PB) + bLaneOff;
    uint32_t bLoAddr = sbase + OFF_W_LO + (uint32_t)(ch * 64 * PB) + bLaneOff;

    __half* xout = dir ? g_xr : g_xf;
    __half* aout = dir ? g_aggr : g_aggf;
    const float* rdegp = dir ? g_rdeg_out : g_rdeg_in;
    const float* dinvp = dir ? g_dinv_out : g_dinv_in;

    int numTiles = (N + 127) / 128;
    int step = gridDim.x >> 1;
    for (int tile = blockIdx.x >> 1; tile < numTiles; tile += step) {
        int base = tile * 128;
        __syncthreads();
        for (int i = tid; i < 128 * 64; i += 512) {
            int r = i >> 6, k2 = (i & 63) << 1;
            int row = base + r;
            float2 v = (row < N) ? *(const float2*)(g_h + (size_t)row * D + k2)
                                 : make_float2(0.f, 0.f);
            *(half2*)((__half*)(smc + OFF_A_HI) + r * PH + k2) = __float22half2_rn(v);
        }
        __syncthreads();

        float acc[8][4];
        #pragma unroll
        for (int nf = 0; nf < 8; nf++)
            #pragma unroll
            for (int j = 0; j < 4; j++) acc[nf][j] = 0.f;

        #pragma unroll 1
        for (int kf = 0; kf < 8; kf++) {
            uint32_t ko = kf * 32;
            uint32_t ah[4];
            ldsm4(ah, aHiAddr + ko);
            #pragma unroll
            for (int nb = 0; nb < 4; nb++) {
                uint32_t boff = (uint32_t)(nb * 16 * PB) + ko;
                uint32_t bh[4], bl[4];
                ldsm4(bh, bHiAddr + boff);
                ldsm4(bl, bLoAddr + boff);
                mma16816(acc[nb * 2],     ah, bh[0], bh[1]);
                mma16816(acc[nb * 2],     ah, bl[0], bl[1]);
                mma16816(acc[nb * 2 + 1], ah, bh[2], bh[3]);
                mma16816(acc[nb * 2 + 1], ah, bl[2], bl[3]);
            }
        }

        int g = lane >> 2, t4 = lane & 3;
        int row0 = base + wm + g;
        int row1 = row0 + 8;
        float di0 = 0.f, rd0 = 0.f, di1 = 0.f, rd1 = 0.f;
        if (row0 < N) { di0 = dinvp[row0]; rd0 = rdegp[row0]; }
        if (row1 < N) { di1 = dinvp[row1]; rd1 = rdegp[row1]; }
        #pragma unroll
        for (int nf = 0; nf < 8; nf++) {
            int col = ch * 64 + nf * 8 + t4 * 2;
            float2 bb = *(const float2*)(sbias + col);
            float2 rr = *(const float2*)(sroot + col);
            if (row0 < N) {
                float v0 = acc[nf][0] + bb.x, v1 = acc[nf][1] + bb.y;
                *(half2*)(xout + (size_t)row0 * D + col) =
                    __floats2half2_rn(fmaxf(v0, 0.f) * di0, fmaxf(v1, 0.f) * di0);
                *(half2*)(aout + (size_t)row0 * D + col) =
                    __floats2half2_rn(fmaxf(v0 + rr.x, 0.f) * rd0, fmaxf(v1 + rr.y, 0.f) * rd0);
            }
            if (row1 < N) {
                float v2 = acc[nf][2] + bb.x, v3 = acc[nf][3] + bb.y;
                *(half2*)(xout + (size_t)row1 * D + col) =
                    __floats2half2_rn(fmaxf(v2, 0.f) * di1, fmaxf(v3, 0.f) * di1);
                *(half2*)(aout + (size_t)row1 * D + col) =
                    __floats2half2_rn(fmaxf(v2 + rr.x, 0.f) * rd1, fmaxf(v3 + rr.y, 0.f) * rd1);
            }
        }
    }
}

// ---------------- fused gather (1 warp/node, 2 neighbors/iter) + LN + residual ----------------
__device__ __forceinline__ void gather_dir_2n(const int* __restrict__ csr, int s0, int s1,
                                              const __half* __restrict__ xs,
                                              int half, int l16, float* acc8)
{
    for (int j = s0; j < s1; j += 32) {
        int nn = s1 - j; if (nn > 32) nn = 32;
        int lane = half * 16 + l16;
        int idx = (lane < nn) ? csr[j + lane] : 0;
        if (nn == 32) {
            #pragma unroll
            for (int k = 0; k < 16; k++) {
                int id = __shfl_sync(0xffffffffu, idx, 2 * k + half);
                uint4 v = *(const uint4*)(xs + (size_t)id * D + l16 * 8);
                float2 f0 = __half22float2(*(half2*)&v.x);
                float2 f1 = __half22float2(*(half2*)&v.y);
                float2 f2 = __half22float2(*(half2*)&v.z);
                float2 f3 = __half22float2(*(half2*)&v.w);
                acc8[0] += f0.x; acc8[1] += f0.y; acc8[2] += f1.x; acc8[3] += f1.y;
                acc8[4] += f2.x; acc8[5] += f2.y; acc8[6] += f3.x; acc8[7] += f3.y;
            }
        } else {
            int pairs = (nn + 1) >> 1;
            for (int k = 0; k < pairs; k++) {
                int slot = 2 * k + half;
                int id = __shfl_sync(0xffffffffu, idx, slot < nn ? slot : 0);
                if (slot < nn) {
                    uint4 v = *(const uint4*)(xs + (size_t)id * D + l16 * 8);
                    float2 f0 = __half22float2(*(half2*)&v.x);
                    float2 f1 = __half22float2(*(half2*)&v.y);
                    float2 f2 = __half22float2(*(half2*)&v.z);
                    float2 f3 = __half22float2(*(half2*)&v.w);
                    acc8[0] += f0.x; acc8[1] += f0.y; acc8[2] += f1.x; acc8[3] += f1.y;
                    acc8[4] += f2.x; acc8[5] += f2.y; acc8[6] += f3.x; acc8[7] += f3.y;
                }
            }
        }
    }
}

__device__ __forceinline__ float4 combine_halves(const float* acc8, int half)
{
    float r[4];
    #pragma unroll
    for (int m = 0; m < 4; m++) {
        float send = half ? acc8[m] : acc8[4 + m];
        float recv = __shfl_xor_sync(0xffffffffu, send, 16);
        float keep = half ? acc8[4 + m] : acc8[m];
        r[m] = keep + recv;
    }
    return make_float4(r[0], r[1], r[2], r[3]);
}

__global__ void gather_post_kernel(const float* __restrict__ lng, const float* __restrict__ lnb,
                                   float* __restrict__ out, int NI, int N, int l)
{
    int gt = blockIdx.x * blockDim.x + threadIdx.x;
    int n = gt >> 5, lane = gt & 31;
    if (n >= N) return;
    int half = lane >> 4, l16 = lane & 15;
    int colb = l16 * 8 + half * 4;

    int si0 = g_off_in[n],  si1 = g_off_in[n + 1];
    int so0 = g_off_out[n], so1 = g_off_out[n + 1];
    float ci = g_dinv_in[n], co = g_dinv_out[n];

    float af8[8], ar8[8];
    #pragma unroll
    for (int j = 0; j < 8; j++) { af8[j] = 0.f; ar8[j] = 0.f; }

    gather_dir_2n(g_csr_in,  si0, si1, g_xf, half, l16, af8);
    gather_dir_2n(g_csr_out, so0, so1, g_xr, half, l16, ar8);

    float4 sf = combine_halves(af8, half);
    float4 sr = combine_halves(ar8, half);

    // self-loop terms (fp16)
    ull va = *(const ull*)(g_aggf + (size_t)n * D + colb);
    ull vr = *(const ull*)(g_aggr + (size_t)n * D + colb);
    float2 a01 = __half22float2(((half2*)&va)[0]);
    float2 a23 = __half22float2(((half2*)&va)[1]);
    float2 r01 = __half22float2(((half2*)&vr)[0]);
    float2 r23 = __half22float2(((half2*)&vr)[1]);

    float4 s;
    s.x = a01.x + sf.x * ci + r01.x + sr.x * co;
    s.y = a01.y + sf.y * ci + r01.y + sr.y * co;
    s.z = a23.x + sf.z * ci + r23.x + sr.z * co;
    s.w = a23.y + sf.w * ci + r23.y + sr.w * co;

    float sum = s.x + s.y + s.z + s.w;
    #pragma unroll
    for (int o = 16; o; o >>= 1) sum += __shfl_xor_sync(0xffffffffu, sum, o);
    float mu = sum * (1.0f / 128.0f);

    float dx = s.x - mu, dy = s.y - mu, dz = s.z - mu, dw = s.w - mu;
    float sq = dx * dx + dy * dy + dz * dz + dw * dw;
    #pragma unroll
    for (int o = 16; o; o >>= 1) sq += __shfl_xor_sync(0xffffffffu, sq, o);
    float rs = rsqrtf(sq * (1.0f / 128.0f) + 1e-5f);

    float4 gg = *(const float4*)(lng + colb);
    float4 bb = *(const float4*)(lnb + colb);
    float4 y;
    y.x = lrelu(dx * rs * gg.x + bb.x);
    y.y = lrelu(dy * rs * gg.y + bb.y);
    y.z = lrelu(dz * rs * gg.z + bb.z);
    y.w = lrelu(dw * rs * gg.w + bb.w);

    float4 h = *(const float4*)(g_h + (size_t)n * D + colb);
    h.x += y.x; h.y += y.y; h.z += y.z; h.w += y.w;
    *(float4*)(g_h + (size_t)n * D + colb) = h;

    if (n >= NI) {
        *(float4*)(out + (size_t)(n - NI) * 512 + (size_t)(l + 1) * 128 + colb) = h;
    }
}

// ---------------- launch ----------------
extern "C" void kernel_launch(void* const* d_in, const int* in_sizes, int n_in,
                              void* d_out, int out_size)
{
    const float* x      = (const float*)d_in[0];
    const float* xnet   = (const float*)d_in[1];
    const float* encW1  = (const float*)d_in[2];
    const float* encb1  = (const float*)d_in[3];
    const float* encW2  = (const float*)d_in[4];
    const float* encb2  = (const float*)d_in[5];
    const float* encnW1 = (const float*)d_in[6];
    const float* encnb1 = (const float*)d_in[7];
    const float* encnW2 = (const float*)d_in[8];
    const float* encnb2 = (const float*)d_in[9];
    const float* convW  = (const float*)d_in[10];
    const float* convb  = (const float*)d_in[11];
    const float* convr  = (const float*)d_in[12];
    const float* rconvW = (const float*)d_in[13];
    const float* rconvb = (const float*)d_in[14];
    const float* rconvr = (const float*)d_in[15];
    const float* lng    = (const float*)d_in[16];
    const float* lnb    = (const float*)d_in[17];
    const int*   src    = (const int*)d_in[18];
    const int*   dst    = (const int*)d_in[19];

    int NI = in_sizes[0] / 11;
    int NN = in_sizes[1] / 3;
    int N  = NI + NN;
    int E  = in_sizes[18];
    float* out = (float*)d_out;

    size_t sm1 = (size_t)(11 * 256 + 256 + 128 * 260 + 128 + 64 * 12 + 64 * 256) * 4;
    cudaFuncSetAttribute(enc_kernel, cudaFuncAttributeMaxDynamicSharedMemorySize, (int)sm1);
    cudaFuncSetAttribute(conv_mma_kernel, cudaFuncAttributeMaxDynamicSharedMemorySize, SMEM_MMA);

    enc_kernel<<<148, 512, sm1>>>(x, xnet, encW1, encb1, encW2, encb2,
                                  encnW1, encnb1, encnW2, encnb2, NI, NN, N, out);
    deg_count_kernel<<<(E + 255) / 256, 256>>>(src, dst, E);
    scan_fin_kernel<<<2, 1024>>>(N, E);
    conv_mma_kernel<<<296, 512, SMEM_MMA>>>(convW, convb, convr, rconvW, rconvb, rconvr, N);
    fill_kernel<<<(E + 255) / 256, 256>>>(src, dst, E);

    int node_threads = N * 32;
    gather_post_kernel<<<(node_threads + 255) / 256, 256>>>(lng, lnb, out, NI, N, 0);

    for (int l = 1; l < 3; l++) {
        conv_mma_kernel<<<296, 512, SMEM_MMA>>>(convW + (size_t)l * 16384, convb + l * 128, convr + l * 128,
                                                rconvW + (size_t)l * 16384, rconvb + l * 128, rconvr + l * 128, N);
        gather_post_kernel<<<(node_threads + 255) / 256, 256>>>(lng + l * 128, lnb + l * 128, out, NI, N, l);
    }
}

// round 16
// speedup vs baseline: 1.1351x; 1.0491x over previous
#include <cuda_runtime.h>
#include <cuda_fp16.h>
#include <cstdint>

#define D 128
#define NMAX 50176
#define EMAX 1048576

typedef unsigned long long ull;

// ---------------- scratch ----------------
static __device__ __align__(16) __half g_h[NMAX * D];    // node features, fp16
static __device__ __align__(16) __half g_xf[NMAX * D];   // dinv_in*relu(xf), fp16
static __device__ __align__(16) __half g_xr[NMAX * D];   // dinv_out*relu(xr), fp16
static __device__ __align__(16) __half g_aggf[NMAX * D]; // self-loop term, fp16
static __device__ __align__(16) __half g_aggr[NMAX * D];
static __device__ float g_deg_in[NMAX];
static __device__ float g_deg_out[NMAX];
static __device__ float g_dinv_in[NMAX];
static __device__ float g_dinv_out[NMAX];
static __device__ float g_rdeg_in[NMAX];
static __device__ float g_rdeg_out[NMAX];
static __device__ int g_off_in[NMAX + 1];
static __device__ int g_off_out[NMAX + 1];
static __device__ int g_fill_in[NMAX];
static __device__ int g_fill_out[NMAX];
static __device__ int g_csr_in[EMAX];
static __device__ int g_csr_out[EMAX];

__device__ __forceinline__ float lrelu(float v) { return v >= 0.f ? v : 0.1f * v; }
__device__ __forceinline__ float4 lrelu4(float4 v) {
    return make_float4(lrelu(v.x), lrelu(v.y), lrelu(v.z), lrelu(v.w));
}
__device__ __forceinline__ void fma2(ull& d, ull a, ull b) {
    asm("fma.rn.f32x2 %0, %1, %2, %0;" : "+l"(d) : "l"(a), "l"(b));
}
__device__ __forceinline__ float unpack_sum(ull v) {
    float2 p = *(float2*)&v;
    return p.x + p.y;
}

// ---------------- mma.sync helpers ----------------
__device__ __forceinline__ uint32_t smem_u32(const void* p) {
    uint32_t a;
    asm("{ .reg .u64 t; cvta.to.shared.u64 t, %1; cvt.u32.u64 %0, t; }" : "=r"(a) : "l"(p));
    return a;
}
__device__ __forceinline__ void ldsm4(uint32_t* r, uint32_t addr) {
    asm volatile("ldmatrix.sync.aligned.m8n8.x4.shared.b16 {%0,%1,%2,%3}, [%4];"
                 : "=r"(r[0]), "=r"(r[1]), "=r"(r[2]), "=r"(r[3]) : "r"(addr));
}
__device__ __forceinline__ void mma16816(float* c, const uint32_t* a, uint32_t b0, uint32_t b1) {
    asm volatile("mma.sync.aligned.m16n8k16.row.col.f32.f16.f16.f32 "
                 "{%0,%1,%2,%3}, {%4,%5,%6,%7}, {%8,%9}, {%0,%1,%2,%3};"
                 : "+f"(c[0]), "+f"(c[1]), "+f"(c[2]), "+f"(c[3])
                 : "r"(a[0]), "r"(a[1]), "r"(a[2]), "r"(a[3]), "r"(b0), "r"(b1));
}

#define NETB 16

// ---------------- fused encoders (+ degree init) ----------------
__global__ void __launch_bounds__(512, 1)
enc_kernel(const float* __restrict__ x, const float* __restrict__ xn,
           const float* __restrict__ W1, const float* __restrict__ b1,
           const float* __restrict__ W2, const float* __restrict__ b2,
           const float* __restrict__ nW1, const float* __restrict__ nb1,
           const float* __restrict__ nW2, const float* __restrict__ nb2,
           int NI, int NN, int N, float* __restrict__ out)
{
    for (int i = blockIdx.x * 512 + threadIdx.x; i < N; i += gridDim.x * 512) {
        g_deg_in[i] = 1.0f; g_deg_out[i] = 1.0f;
    }

    extern __shared__ float sm[];
    int tid = threadIdx.x;

    if (blockIdx.x < NETB) {
        // ---- net path: 3 -> 128 -> 128 ----
        float* sW1  = sm;
        float* sb1  = sW1 + 128 * 3;
        float* sW2  = sb1 + 128;          // [c][k] stride 132
        float* sb2  = sW2 + 128 * 132;
        float* sX   = sb2 + 128;
        float* st   = sX + 64 * 4;

        for (int i = tid; i < 128 * 3; i += 512) sW1[i] = nW1[i];
        if (tid < 128) sb1[tid] = nb1[tid];
        for (int i = tid; i < 128 * 128; i += 512) {
            int c = i >> 7, k = i & 127;
            sW2[c * 132 + k] = nW2[i];
        }
        if (tid < 128) sb2[tid] = nb2[tid];
        __syncthreads();

        int rg2 = tid >> 5;
        int cg  = tid & 31;

        int numTiles = (NN + 63) / 64;
        for (int tile = blockIdx.x; tile < numTiles; tile += NETB) {
            int base = tile * 64;
            __syncthreads();
            for (int i = tid; i < 64 * 3; i += 512) {
                int r = i / 3, p = i % 3;
                int row = base + r;
                sX[r * 4 + p] = (row < NN) ? xn[(size_t)row * 3 + p] : 0.f;
            }
            __syncthreads();
            for (int i = tid; i < 64 * 128; i += 512) {
                int r = i >> 7, j = i & 127;
                float a = sb1[j] + sX[r * 4] * sW1[j * 3] + sX[r * 4 + 1] * sW1[j * 3 + 1]
                        + sX[r * 4 + 2] * sW1[j * 3 + 2];
                st[i] = lrelu(a);
            }
            __syncthreads();

            ull acc[4][4];
            #pragma unroll
            for (int r = 0; r < 4; r++)
                #pragma unroll
                for (int j = 0; j < 4; j++) acc[r][j] = 0ull;

            const float* tb = st + rg2 * 4 * 128;
            #pragma unroll 2
            for (int k = 0; k < 128; k += 4) {
                ull w01[4], w23[4];
                #pragma unroll
                for (int j = 0; j < 4; j++) {
                    float4 w = *(const float4*)(sW2 + (cg + 32 * j) * 132 + k);
                    w01[j] = ((ull*)&w)[0]; w23[j] = ((ull*)&w)[1];
                }
                #pragma unroll
                for (int r = 0; r < 4; r++) {
                    float4 h4 = *(const float4*)(tb + r * 128 + k);
                    ull h01 = ((ull*)&h4)[0], h23 = ((ull*)&h4)[1];
                    #pragma unroll
                    for (int j = 0; j < 4; j++) {
                        fma2(acc[r][j], h01, w01[j]);
                        fma2(acc[r][j], h23, w23[j]);
                    }
                }
            }
            #pragma unroll
            for (int r = 0; r < 4; r++) {
                int row = base + rg2 * 4 + r;
                if (row < NN) {
                    #pragma unroll
                    for (int j = 0; j < 4; j++) {
                        int c = cg + 32 * j;
                        float v = lrelu(unpack_sum(acc[r][j]) + sb2[c]);
                        g_h[(size_t)(NI + row) * D + c] = __float2half_rn(v);
                        out[(size_t)row * 512 + c] = v;
                    }
                }
            }
        }
    } else {
        // ---- instance path: 11 -> 256 -> 128 ----
        float* sW1T = sm;
        float* sb1  = sW1T + 11 * 256;
        float* sW2  = sb1 + 256;          // [c][k] stride 260
        float* sb2  = sW2 + 128 * 260;
        float* sX   = sb2 + 128;
        float* st   = sX + 64 * 12;

        for (int i = tid; i < 256 * 11; i += 512) {
            int j = i / 11, p = i % 11;
            sW1T[p * 256 + j] = W1[i];
        }
        if (tid < 256) sb1[tid] = b1[tid];
        for (int i = tid; i < 128 * 256; i += 512) {
            int c = i >> 8, k = i & 255;
            sW2[c * 260 + k] = W2[i];
        }
        if (tid < 128) sb2[tid] = b2[tid];
        __syncthreads();

        int rg1 = tid >> 6;
        int jg  = tid & 63;
        float4 b1v = *(const float4*)(sb1 + jg * 4);

        int rg2 = tid >> 5;
        int cg  = tid & 31;

        int nb = gridDim.x - NETB;
        int numTiles = (NI + 63) / 64;
        for (int tile = blockIdx.x - NETB; tile < numTiles; tile += nb) {
            int base = tile * 64;
            __syncthreads();
            for (int i = tid; i < 64 * 11; i += 512) {
                int r = i / 11, p = i % 11;
                int row = base + r;
                sX[r * 12 + p] = (row < NI) ? x[(size_t)row * 11 + p] : 0.f;
            }
            __syncthreads();

            {
                float4 acc[8];
                #pragma unroll
                for (int r = 0; r < 8; r++) acc[r] = b1v;
                #pragma unroll
                for (int p = 0; p < 11; p++) {
                    float4 w = *(const float4*)(sW1T + p * 256 + jg * 4);
                    #pragma unroll
                    for (int r = 0; r < 8; r++) {
                        float xv = sX[(rg1 * 8 + r) * 12 + p];
                        acc[r].x += xv * w.x; acc[r].y += xv * w.y;
                        acc[r].z += xv * w.z; acc[r].w += xv * w.w;
                    }
                }
                #pragma unroll
                for (int r = 0; r < 8; r++)
                    *(float4*)(st + (rg1 * 8 + r) * 256 + jg * 4) = lrelu4(acc[r]);
            }
            __syncthreads();

            {
                ull acc[4][4];
                #pragma unroll
                for (int r = 0; r < 4; r++)
                    #pragma unroll
                    for (int j = 0; j < 4; j++) acc[r][j] = 0ull;

                const float* tb = st + rg2 * 4 * 256;
                #pragma unroll 2
                for (int k = 0; k < 256; k += 4) {
                    ull w01[4], w23[4];
                    #pragma unroll
                    for (int j = 0; j < 4; j++) {
                        float4 w = *(const float4*)(sW2 + (cg + 32 * j) * 260 + k);
                        w01[j] = ((ull*)&w)[0]; w23[j] = ((ull*)&w)[1];
                    }
                    #pragma unroll
                    for (int r = 0; r < 4; r++) {
                        float4 h4 = *(const float4*)(tb + r * 256 + k);
                        ull h01 = ((ull*)&h4)[0], h23 = ((ull*)&h4)[1];
                        #pragma unroll
                        for (int j = 0; j < 4; j++) {
                            fma2(acc[r][j], h01, w01[j]);
                            fma2(acc[r][j], h23, w23[j]);
                        }
                    }
                }
                #pragma unroll
                for (int r = 0; r < 4; r++) {
                    int row = base + rg2 * 4 + r;
                    if (row < NI) {
                        #pragma unroll
                        for (int j = 0; j < 4; j++) {
                            int c = cg + 32 * j;
                            float v = lrelu(unpack_sum(acc[r][j]) + sb2[c]);
                            g_h[(size_t)row * D + c] = __float2half_rn(v);
                        }
                    }
                }
            }
        }
    }
}

// ---------------- degree count ----------------
__global__ void deg_count_kernel(const int* __restrict__ src, const int* __restrict__ dst, int E)
{
    int e = blockIdx.x * blockDim.x + threadIdx.x;
    if (e < E) {
        atomicAdd(&g_deg_in[dst[e]], 1.0f);
        atomicAdd(&g_deg_out[src[e]], 1.0f);
    }
}

// ---------------- scan + fin ----------------
__global__ void scan_fin_kernel(int N, int E)
{
    __shared__ int warp_sums[32];
    __shared__ int warp_offs[32];
    __shared__ int chunk_tot;
    __shared__ int carry_s;
    const float* deg = (blockIdx.x == 0) ? g_deg_in : g_deg_out;
    int* off = (blockIdx.x == 0) ? g_off_in : g_off_out;
    int tid = threadIdx.x, lane = tid & 31, wid = tid >> 5;
    if (tid == 0) carry_s = 0;
    __syncthreads();
    for (int base = 0; base < N; base += 1024) {
        int i = base + tid;
        int v = (i < N) ? ((int)deg[i]) - 1 : 0;
        int incl = v;
        #pragma unroll
        for (int o = 1; o < 32; o <<= 1) {
            int t = __shfl_up_sync(0xffffffffu, incl, o);
            if (lane >= o) incl += t;
        }
        if (lane == 31) warp_sums[wid] = incl;
        __syncthreads();
        if (wid == 0) {
            int ws = warp_sums[lane];
            int wi = ws;
            #pragma unroll
            for (int o = 1; o < 32; o <<= 1) {
                int t = __shfl_up_sync(0xffffffffu, wi, o);
                if (lane >= o) wi += t;
            }
            warp_offs[lane] = wi - ws;
            if (lane == 31) chunk_tot = wi;
        }
        __syncthreads();
        if (i < N) off[i] = carry_s + warp_offs[wid] + incl - v;
        __syncthreads();
        if (tid == 0) carry_s += chunk_tot;
    }
    if (tid == 0) off[N] = E;
    if (blockIdx.x == 0) {
        for (int i = tid; i < N; i += 1024) {
            float a = g_deg_in[i];
            g_dinv_in[i] = rsqrtf(a);
            g_rdeg_in[i] = 1.0f / a;
            g_fill_in[i] = 0;
        }
    } else {
        for (int i = tid; i < N; i += 1024) {
            float a = g_deg_out[i];
            g_dinv_out[i] = rsqrtf(a);
            g_rdeg_out[i] = 1.0f / a;
            g_fill_out[i] = 0;
        }
    }
}

__global__ void fill_kernel(const int* __restrict__ src, const int* __restrict__ dst, int E)
{
    int e = blockIdx.x * blockDim.x + threadIdx.x;
    if (e < E) {
        int s = src[e], d = dst[e];
        int p = atomicAdd(&g_fill_in[d], 1);
        g_csr_in[g_off_in[d] + p] = s;
        int q = atomicAdd(&g_fill_out[s], 1);
        g_csr_out[g_off_out[s] + q] = d;
    }
}

// ---------------- per-layer dense part: mma.sync 2-term split, one direction per CTA ----------------
#define PH 136       // smem pitch in halves
#define PB 272       // smem pitch in bytes
#define TILE_B (128 * PB)          // 34816
#define OFF_W_HI 0
#define OFF_W_LO (1 * TILE_B)
#define OFF_A_HI (2 * TILE_B)
#define OFF_BIAS (3 * TILE_B)      // float[128]
#define OFF_ROOT (3 * TILE_B + 512)
#define SMEM_MMA (3 * TILE_B + 1024)   // 105472

__global__ void __launch_bounds__(512, 2)
conv_mma_kernel(const float* __restrict__ Wf, const float* __restrict__ bf,
                const float* __restrict__ rootf,
                const float* __restrict__ Wr, const float* __restrict__ br,
                const float* __restrict__ rootr, int N)
{
    extern __shared__ __align__(16) char smc[];
    uint32_t sbase = smem_u32(smc);
    int tid = threadIdx.x;
    int dir = blockIdx.x & 1;

    const float* Wg = dir ? Wr : Wf;
    const float* bg = dir ? br : bf;
    const float* rg_g = dir ? rootr : rootf;

    float* sbias = (float*)(smc + OFF_BIAS);
    float* sroot = (float*)(smc + OFF_ROOT);
    if (tid < 128) { sbias[tid] = bg[tid]; sroot[tid] = rg_g[tid]; }

    for (int i = tid; i < 128 * 64; i += 512) {
        int c = i >> 6, k2 = (i & 63) << 1;
        int ho = c * PH + k2;
        float2 wv = *(const float2*)(Wg + c * 128 + k2);
        half2 hv = __float22half2_rn(wv);
        float2 bk = __half22float2(hv);
        *(half2*)((__half*)(smc + OFF_W_HI) + ho) = hv;
        *(half2*)((__half*)(smc + OFF_W_LO) + ho) =
            __float22half2_rn(make_float2(wv.x - bk.x, wv.y - bk.y));
    }
    __syncthreads();

    int w = tid >> 5, lane = tid & 31;
    int rg = w >> 1;          // 0..7: 16-row group
    int ch = w & 1;           // 0/1: 64-col half
    int wm = rg * 16;

    uint32_t aLaneOff = (uint32_t)((wm + (lane & 15)) * PB + ((lane >> 4) << 4));
    uint32_t bLaneOff = (uint32_t)(((((lane >> 4) << 3) + (lane & 7)) * PB) + ((((lane >> 3) & 1)) << 4));
    uint32_t aHiAddr = sbase + OFF_A_HI + aLaneOff;
    uint32_t bHiAddr = sbase + OFF_W_HI + (uint32_t)(ch * 64 * PB) + bLaneOff;
    uint32_t bLoAddr = sbase + OFF_W_LO + (uint32_t)(ch * 64 * PB) + bLaneOff;

    __half* xout = dir ? g_xr : g_xf;
    __half* aout = dir ? g_aggr : g_aggf;
    const float* rdegp = dir ? g_rdeg_out : g_rdeg_in;
    const float* dinvp = dir ? g_dinv_out : g_dinv_in;

    int numTiles = (N + 127) / 128;
    int step = gridDim.x >> 1;
    for (int tile = blockIdx.x >> 1; tile < numTiles; tile += step) {
        int base = tile * 128;
        __syncthreads();
        // stage A: straight 16B copies (h already fp16)
        for (int i = tid; i < 128 * 16; i += 512) {
            int r = i >> 4, k8 = (i & 15) << 3;
            int row = base + r;
            uint4 v = make_uint4(0u, 0u, 0u, 0u);
            if (row < N) v = *(const uint4*)(g_h + (size_t)row * D + k8);
            *(uint4*)((__half*)(smc + OFF_A_HI) + r * PH + k8) = v;
        }
        __syncthreads();

        float acc[8][4];
        #pragma unroll
        for (int nf = 0; nf < 8; nf++)
            #pragma unroll
            for (int j = 0; j < 4; j++) acc[nf][j] = 0.f;

        #pragma unroll 1
        for (int kf = 0; kf < 8; kf++) {
            uint32_t ko = kf * 32;
            uint32_t ah[4];
            ldsm4(ah, aHiAddr + ko);
            #pragma unroll
            for (int nb = 0; nb < 4; nb++) {
                uint32_t boff = (uint32_t)(nb * 16 * PB) + ko;
                uint32_t bh[4], bl[4];
                ldsm4(bh, bHiAddr + boff);
                ldsm4(bl, bLoAddr + boff);
                mma16816(acc[nb * 2],     ah, bh[0], bh[1]);
                mma16816(acc[nb * 2],     ah, bl[0], bl[1]);
                mma16816(acc[nb * 2 + 1], ah, bh[2], bh[3]);
                mma16816(acc[nb * 2 + 1], ah, bl[2], bl[3]);
            }
        }

        int g = lane >> 2, t4 = lane & 3;
        int row0 = base + wm + g;
        int row1 = row0 + 8;
        float di0 = 0.f, rd0 = 0.f, di1 = 0.f, rd1 = 0.f;
        if (row0 < N) { di0 = dinvp[row0]; rd0 = rdegp[row0]; }
        if (row1 < N) { di1 = dinvp[row1]; rd1 = rdegp[row1]; }
        #pragma unroll
        for (int nf = 0; nf < 8; nf++) {
            int col = ch * 64 + nf * 8 + t4 * 2;
            float2 bb = *(const float2*)(sbias + col);
            float2 rr = *(const float2*)(sroot + col);
            if (row0 < N) {
                float v0 = acc[nf][0] + bb.x, v1 = acc[nf][1] + bb.y;
                *(half2*)(xout + (size_t)row0 * D + col) =
                    __floats2half2_rn(fmaxf(v0, 0.f) * di0, fmaxf(v1, 0.f) * di0);
                *(half2*)(aout + (size_t)row0 * D + col) =
                    __floats2half2_rn(fmaxf(v0 + rr.x, 0.f) * rd0, fmaxf(v1 + rr.y, 0.f) * rd0);
            }
            if (row1 < N) {
                float v2 = acc[nf][2] + bb.x, v3 = acc[nf][3] + bb.y;
                *(half2*)(xout + (size_t)row1 * D + col) =
                    __floats2half2_rn(fmaxf(v2, 0.f) * di1, fmaxf(v3, 0.f) * di1);
                *(half2*)(aout + (size_t)row1 * D + col) =
                    __floats2half2_rn(fmaxf(v2 + rr.x, 0.f) * rd1, fmaxf(v3 + rr.y, 0.f) * rd1);
            }
        }
    }
}

// ---------------- fused gather (1 warp/node, 2 neighbors/iter) + LN + residual ----------------
__device__ __forceinline__ void gather_dir_2n(const int* __restrict__ csr, int s0, int s1,
                                              const __half* __restrict__ xs,
                                              int half, int l16, float* acc8)
{
    for (int j = s0; j < s1; j += 32) {
        int nn = s1 - j; if (nn > 32) nn = 32;
        int lane = half * 16 + l16;
        int idx = (lane < nn) ? csr[j + lane] : 0;
        if (nn == 32) {
            #pragma unroll
            for (int k = 0; k < 16; k++) {
                int id = __shfl_sync(0xffffffffu, idx, 2 * k + half);
                uint4 v = *(const uint4*)(xs + (size_t)id * D + l16 * 8);
                float2 f0 = __half22float2(*(half2*)&v.x);
                float2 f1 = __half22float2(*(half2*)&v.y);
                float2 f2 = __half22float2(*(half2*)&v.z);
                float2 f3 = __half22float2(*(half2*)&v.w);
                acc8[0] += f0.x; acc8[1] += f0.y; acc8[2] += f1.x; acc8[3] += f1.y;
                acc8[4] += f2.x; acc8[5] += f2.y; acc8[6] += f3.x; acc8[7] += f3.y;
            }
        } else {
            int pairs = (nn + 1) >> 1;
            for (int k = 0; k < pairs; k++) {
                int slot = 2 * k + half;
                int id = __shfl_sync(0xffffffffu, idx, slot < nn ? slot : 0);
                if (slot < nn) {
                    uint4 v = *(const uint4*)(xs + (size_t)id * D + l16 * 8);
                    float2 f0 = __half22float2(*(half2*)&v.x);
                    float2 f1 = __half22float2(*(half2*)&v.y);
                    float2 f2 = __half22float2(*(half2*)&v.z);
                    float2 f3 = __half22float2(*(half2*)&v.w);
                    acc8[0] += f0.x; acc8[1] += f0.y; acc8[2] += f1.x; acc8[3] += f1.y;
                    acc8[4] += f2.x; acc8[5] += f2.y; acc8[6] += f3.x; acc8[7] += f3.y;
                }
            }
        }
    }
}

__device__ __forceinline__ float4 combine_halves(const float* acc8, int half)
{
    float r[4];
    #pragma unroll
    for (int m = 0; m < 4; m++) {
        float send = half ? acc8[m] : acc8[4 + m];
        float recv = __shfl_xor_sync(0xffffffffu, send, 16);
        float keep = half ? acc8[4 + m] : acc8[m];
        r[m] = keep + recv;
    }
    return make_float4(r[0], r[1], r[2], r[3]);
}

__global__ void gather_post_kernel(const float* __restrict__ lng, const float* __restrict__ lnb,
                                   float* __restrict__ out, int NI, int N, int l)
{
    int gt = blockIdx.x * blockDim.x + threadIdx.x;
    int n = gt >> 5, lane = gt & 31;
    if (n >= N) return;
    int half = lane >> 4, l16 = lane & 15;
    int colb = l16 * 8 + half * 4;

    int si0 = g_off_in[n],  si1 = g_off_in[n + 1];
    int so0 = g_off_out[n], so1 = g_off_out[n + 1];
    float ci = g_dinv_in[n], co = g_dinv_out[n];

    float af8[8], ar8[8];
    #pragma unroll
    for (int j = 0; j < 8; j++) { af8[j] = 0.f; ar8[j] = 0.f; }

    gather_dir_2n(g_csr_in,  si0, si1, g_xf, half, l16, af8);
    gather_dir_2n(g_csr_out, so0, so1, g_xr, half, l16, ar8);

    float4 sf = combine_halves(af8, half);
    float4 sr = combine_halves(ar8, half);

    // self-loop terms (fp16)
    ull va = *(const ull*)(g_aggf + (size_t)n * D + colb);
    ull vr = *(const ull*)(g_aggr + (size_t)n * D + colb);
    float2 a01 = __half22float2(((half2*)&va)[0]);
    float2 a23 = __half22float2(((half2*)&va)[1]);
    float2 r01 = __half22float2(((half2*)&vr)[0]);
    float2 r23 = __half22float2(((half2*)&vr)[1]);

    float4 s;
    s.x = a01.x + sf.x * ci + r01.x + sr.x * co;
    s.y = a01.y + sf.y * ci + r01.y + sr.y * co;
    s.z = a23.x + sf.z * ci + r23.x + sr.z * co;
    s.w = a23.y + sf.w * ci + r23.y + sr.w * co;

    float sum = s.x + s.y + s.z + s.w;
    #pragma unroll
    for (int o = 16; o; o >>= 1) sum += __shfl_xor_sync(0xffffffffu, sum, o);
    float mu = sum * (1.0f / 128.0f);

    float dx = s.x - mu, dy = s.y - mu, dz = s.z - mu, dw = s.w - mu;
    float sq = dx * dx + dy * dy + dz * dz + dw * dw;
    #pragma unroll
    for (int o = 16; o; o >>= 1) sq += __shfl_xor_sync(0xffffffffu, sq, o);
    float rs = rsqrtf(sq * (1.0f / 128.0f) + 1e-5f);

    float4 gg = *(const float4*)(lng + colb);
    float4 bb = *(const float4*)(lnb + colb);
    float4 y;
    y.x = lrelu(dx * rs * gg.x + bb.x);
    y.y = lrelu(dy * rs * gg.y + bb.y);
    y.z = lrelu(dz * rs * gg.z + bb.z);
    y.w = lrelu(dw * rs * gg.w + bb.w);

    // residual in fp16 h
    ull vh = *(const ull*)(g_h + (size_t)n * D + colb);
    float2 h01 = __half22float2(((half2*)&vh)[0]);
    float2 h23 = __half22float2(((half2*)&vh)[1]);
    float4 h;
    h.x = h01.x + y.x; h.y = h01.y + y.y; h.z = h23.x + y.z; h.w = h23.y + y.w;

    ull vo;
    ((half2*)&vo)[0] = __floats2half2_rn(h.x, h.y);
    ((half2*)&vo)[1] = __floats2half2_rn(h.z, h.w);
    *(ull*)(g_h + (size_t)n * D + colb) = vo;

    if (n >= NI) {
        *(float4*)(out + (size_t)(n - NI) * 512 + (size_t)(l + 1) * 128 + colb) = h;
    }
}

// ---------------- launch ----------------
extern "C" void kernel_launch(void* const* d_in, const int* in_sizes, int n_in,
                              void* d_out, int out_size)
{
    const float* x      = (const float*)d_in[0];
    const float* xnet   = (const float*)d_in[1];
    const float* encW1  = (const float*)d_in[2];
    const float* encb1  = (const float*)d_in[3];
    const float* encW2  = (const float*)d_in[4];
    const float* encb2  = (const float*)d_in[5];
    const float* encnW1 = (const float*)d_in[6];
    const float* encnb1 = (const float*)d_in[7];
    const float* encnW2 = (const float*)d_in[8];
    const float* encnb2 = (const float*)d_in[9];
    const float* convW  = (const float*)d_in[10];
    const float* convb  = (const float*)d_in[11];
    const float* convr  = (const float*)d_in[12];
    const float* rconvW = (const float*)d_in[13];
    const float* rconvb = (const float*)d_in[14];
    const float* rconvr = (const float*)d_in[15];
    const float* lng    = (const float*)d_in[16];
    const float* lnb    = (const float*)d_in[17];
    const int*   src    = (const int*)d_in[18];
    const int*   dst    = (const int*)d_in[19];

    int NI = in_sizes[0] / 11;
    int NN = in_sizes[1] / 3;
    int N  = NI + NN;
    int E  = in_sizes[18];
    float* out = (float*)d_out;

    size_t sm1 = (size_t)(11 * 256 + 256 + 128 * 260 + 128 + 64 * 12 + 64 * 256) * 4;
    cudaFuncSetAttribute(enc_kernel, cudaFuncAttributeMaxDynamicSharedMemorySize, (int)sm1);
    cudaFuncSetAttribute(conv_mma_kernel, cudaFuncAttributeMaxDynamicSharedMemorySize, SMEM_MMA);

    enc_kernel<<<148, 512, sm1>>>(x, xnet, encW1, encb1, encW2, encb2,
                                  encnW1, encnb1, encnW2, encnb2, NI, NN, N, out);
    deg_count_kernel<<<(E + 255) / 256, 256>>>(src, dst, E);
    scan_fin_kernel<<<2, 1024>>>(N, E);
    conv_mma_kernel<<<296, 512, SMEM_MMA>>>(convW, convb, convr, rconvW, rconvb, rconvr, N);
    fill_kernel<<<(E + 255) / 256, 256>>>(src, dst, E);

    int node_threads = N * 32;
    gather_post_kernel<<<(node_threads + 255) / 256, 256>>>(lng, lnb, out, NI, N, 0);

    for (int l = 1; l < 3; l++) {
        conv_mma_kernel<<<296, 512, SMEM_MMA>>>(convW + (size_t)l * 16384, convb + l * 128, convr + l * 128,
                                                rconvW + (size_t)l * 16384, rconvb + l * 128, rconvr + l * 128, N);
        gather_post_kernel<<<(node_threads + 255) / 256, 256>>>(lng + l * 128, lnb + l * 128, out, NI, N, l);
    }
}

// round 17
// speedup vs baseline: 1.1568x; 1.0191x over previous
#include <cuda_runtime.h>
#include <cuda_fp16.h>
#include <cstdint>

#define D 128
#define NMAX 50176
#define EMAX 1048576

typedef unsigned long long ull;

// ---------------- scratch ----------------
static __device__ __align__(16) __half g_h[NMAX * D];    // node features, fp16
static __device__ __align__(16) __half g_xf[NMAX * D];   // dinv_in*relu(xf), fp16
static __device__ __align__(16) __half g_xr[NMAX * D];   // dinv_out*relu(xr), fp16
static __device__ __align__(16) __half g_aggf[NMAX * D]; // self-loop term, fp16
static __device__ __align__(16) __half g_aggr[NMAX * D];
static __device__ float g_deg_in[NMAX];
static __device__ float g_deg_out[NMAX];
static __device__ float g_dinv_in[NMAX];
static __device__ float g_dinv_out[NMAX];
static __device__ float g_rdeg_in[NMAX];
static __device__ float g_rdeg_out[NMAX];
static __device__ int g_off_in[NMAX + 1];
static __device__ int g_off_out[NMAX + 1];
static __device__ int g_fill_in[NMAX];
static __device__ int g_fill_out[NMAX];
static __device__ int g_csr_in[EMAX];
static __device__ int g_csr_out[EMAX];

__device__ __forceinline__ float lrelu(float v) { return v >= 0.f ? v : 0.1f * v; }
__device__ __forceinline__ float4 lrelu4(float4 v) {
    return make_float4(lrelu(v.x), lrelu(v.y), lrelu(v.z), lrelu(v.w));
}
__device__ __forceinline__ void fma2(ull& d, ull a, ull b) {
    asm("fma.rn.f32x2 %0, %1, %2, %0;" : "+l"(d) : "l"(a), "l"(b));
}
__device__ __forceinline__ float unpack_sum(ull v) {
    float2 p = *(float2*)&v;
    return p.x + p.y;
}

// ---------------- mma.sync helpers ----------------
__device__ __forceinline__ uint32_t smem_u32(const void* p) {
    uint32_t a;
    asm("{ .reg .u64 t; cvta.to.shared.u64 t, %1; cvt.u32.u64 %0, t; }" : "=r"(a) : "l"(p));
    return a;
}
__device__ __forceinline__ void ldsm4(uint32_t* r, uint32_t addr) {
    asm volatile("ldmatrix.sync.aligned.m8n8.x4.shared.b16 {%0,%1,%2,%3}, [%4];"
                 : "=r"(r[0]), "=r"(r[1]), "=r"(r[2]), "=r"(r[3]) : "r"(addr));
}
__device__ __forceinline__ void mma16816(float* c, const uint32_t* a, uint32_t b0, uint32_t b1) {
    asm volatile("mma.sync.aligned.m16n8k16.row.col.f32.f16.f16.f32 "
                 "{%0,%1,%2,%3}, {%4,%5,%6,%7}, {%8,%9}, {%0,%1,%2,%3};"
                 : "+f"(c[0]), "+f"(c[1]), "+f"(c[2]), "+f"(c[3])
                 : "r"(a[0]), "r"(a[1]), "r"(a[2]), "r"(a[3]), "r"(b0), "r"(b1));
}

#define NETB 16

// ---------------- fused encoders ----------------
__global__ void __launch_bounds__(512, 1)
enc_kernel(const float* __restrict__ x, const float* __restrict__ xn,
           const float* __restrict__ W1, const float* __restrict__ b1,
           const float* __restrict__ W2, const float* __restrict__ b2,
           const float* __restrict__ nW1, const float* __restrict__ nb1,
           const float* __restrict__ nW2, const float* __restrict__ nb2,
           int NI, int NN, int N, float* __restrict__ out)
{
    extern __shared__ float sm[];
    int tid = threadIdx.x;

    if (blockIdx.x < NETB) {
        // ---- net path: 3 -> 128 -> 128 ----
        float* sW1  = sm;
        float* sb1  = sW1 + 128 * 3;
        float* sW2  = sb1 + 128;          // [c][k] stride 132
        float* sb2  = sW2 + 128 * 132;
        float* sX   = sb2 + 128;
        float* st   = sX + 64 * 4;

        for (int i = tid; i < 128 * 3; i += 512) sW1[i] = nW1[i];
        if (tid < 128) sb1[tid] = nb1[tid];
        for (int i = tid; i < 128 * 128; i += 512) {
            int c = i >> 7, k = i & 127;
            sW2[c * 132 + k] = nW2[i];
        }
        if (tid < 128) sb2[tid] = nb2[tid];
        __syncthreads();

        int rg2 = tid >> 5;
        int cg  = tid & 31;

        int numTiles = (NN + 63) / 64;
        for (int tile = blockIdx.x; tile < numTiles; tile += NETB) {
            int base = tile * 64;
            __syncthreads();
            for (int i = tid; i < 64 * 3; i += 512) {
                int r = i / 3, p = i % 3;
                int row = base + r;
                sX[r * 4 + p] = (row < NN) ? xn[(size_t)row * 3 + p] : 0.f;
            }
            __syncthreads();
            for (int i = tid; i < 64 * 128; i += 512) {
                int r = i >> 7, j = i & 127;
                float a = sb1[j] + sX[r * 4] * sW1[j * 3] + sX[r * 4 + 1] * sW1[j * 3 + 1]
                        + sX[r * 4 + 2] * sW1[j * 3 + 2];
                st[i] = lrelu(a);
            }
            __syncthreads();

            ull acc[4][4];
            #pragma unroll
            for (int r = 0; r < 4; r++)
                #pragma unroll
                for (int j = 0; j < 4; j++) acc[r][j] = 0ull;

            const float* tb = st + rg2 * 4 * 128;
            #pragma unroll 2
            for (int k = 0; k < 128; k += 4) {
                ull w01[4], w23[4];
                #pragma unroll
                for (int j = 0; j < 4; j++) {
                    float4 w = *(const float4*)(sW2 + (cg + 32 * j) * 132 + k);
                    w01[j] = ((ull*)&w)[0]; w23[j] = ((ull*)&w)[1];
                }
                #pragma unroll
                for (int r = 0; r < 4; r++) {
                    float4 h4 = *(const float4*)(tb + r * 128 + k);
                    ull h01 = ((ull*)&h4)[0], h23 = ((ull*)&h4)[1];
                    #pragma unroll
                    for (int j = 0; j < 4; j++) {
                        fma2(acc[r][j], h01, w01[j]);
                        fma2(acc[r][j], h23, w23[j]);
                    }
                }
            }
            #pragma unroll
            for (int r = 0; r < 4; r++) {
                int row = base + rg2 * 4 + r;
                if (row < NN) {
                    #pragma unroll
                    for (int j = 0; j < 4; j++) {
                        int c = cg + 32 * j;
                        float v = lrelu(unpack_sum(acc[r][j]) + sb2[c]);
                        g_h[(size_t)(NI + row) * D + c] = __float2half_rn(v);
                        out[(size_t)row * 512 + c] = v;
                    }
                }
            }
        }
    } else {
        // ---- instance path: 11 -> 256 -> 128 ----
        float* sW1T = sm;
        float* sb1  = sW1T + 11 * 256;
        float* sW2  = sb1 + 256;          // [c][k] stride 260
        float* sb2  = sW2 + 128 * 260;
        float* sX   = sb2 + 128;
        float* st   = sX + 64 * 12;

        for (int i = tid; i < 256 * 11; i += 512) {
            int j = i / 11, p = i % 11;
            sW1T[p * 256 + j] = W1[i];
        }
        if (tid < 256) sb1[tid] = b1[tid];
        for (int i = tid; i < 128 * 256; i += 512) {
            int c = i >> 8, k = i & 255;
            sW2[c * 260 + k] = W2[i];
        }
        if (tid < 128) sb2[tid] = b2[tid];
        __syncthreads();

        int rg1 = tid >> 6;
        int jg  = tid & 63;
        float4 b1v = *(const float4*)(sb1 + jg * 4);

        int rg2 = tid >> 5;
        int cg  = tid & 31;

        int nb = gridDim.x - NETB;
        int numTiles = (NI + 63) / 64;
        for (int tile = blockIdx.x - NETB; tile < numTiles; tile += nb) {
            int base = tile * 64;
            __syncthreads();
            for (int i = tid; i < 64 * 11; i += 512) {
                int r = i / 11, p = i % 11;
                int row = base + r;
                sX[r * 12 + p] = (row < NI) ? x[(size_t)row * 11 + p] : 0.f;
            }
            __syncthreads();

            {
                float4 acc[8];
                #pragma unroll
                for (int r = 0; r < 8; r++) acc[r] = b1v;
                #pragma unroll
                for (int p = 0; p < 11; p++) {
                    float4 w = *(const float4*)(sW1T + p * 256 + jg * 4);
                    #pragma unroll
                    for (int r = 0; r < 8; r++) {
                        float xv = sX[(rg1 * 8 + r) * 12 + p];
                        acc[r].x += xv * w.x; acc[r].y += xv * w.y;
                        acc[r].z += xv * w.z; acc[r].w += xv * w.w;
                    }
                }
                #pragma unroll
                for (int r = 0; r < 8; r++)
                    *(float4*)(st + (rg1 * 8 + r) * 256 + jg * 4) = lrelu4(acc[r]);
            }
            __syncthreads();

            {
                ull acc[4][4];
                #pragma unroll
                for (int r = 0; r < 4; r++)
                    #pragma unroll
                    for (int j = 0; j < 4; j++) acc[r][j] = 0ull;

                const float* tb = st + rg2 * 4 * 256;
                #pragma unroll 2
                for (int k = 0; k < 256; k += 4) {
                    ull w01[4], w23[4];
                    #pragma unroll
                    for (int j = 0; j < 4; j++) {
                        float4 w = *(const float4*)(sW2 + (cg + 32 * j) * 260 + k);
                        w01[j] = ((ull*)&w)[0]; w23[j] = ((ull*)&w)[1];
                    }
                    #pragma unroll
                    for (int r = 0; r < 4; r++) {
                        float4 h4 = *(const float4*)(tb + r * 256 + k);
                        ull h01 = ((ull*)&h4)[0], h23 = ((ull*)&h4)[1];
                        #pragma unroll
                        for (int j = 0; j < 4; j++) {
                            fma2(acc[r][j], h01, w01[j]);
                            fma2(acc[r][j], h23, w23[j]);
                        }
                    }
                }
                #pragma unroll
                for (int r = 0; r < 4; r++) {
                    int row = base + rg2 * 4 + r;
                    if (row < NI) {
                        #pragma unroll
                        for (int j = 0; j < 4; j++) {
                            int c = cg + 32 * j;
                            float v = lrelu(unpack_sum(acc[r][j]) + sb2[c]);
                            g_h[(size_t)row * D + c] = __float2half_rn(v);
                        }
                    }
                }
            }
        }
    }
}

// ---------------- degree init + count ----------------
__global__ void deg_init_kernel(int N)
{
    int i = blockIdx.x * blockDim.x + threadIdx.x;
    if (i < N) { g_deg_in[i] = 1.0f; g_deg_out[i] = 1.0f; }
}

__global__ void deg_count_kernel(const int* __restrict__ src, const int* __restrict__ dst, int E)
{
    int e = blockIdx.x * blockDim.x + threadIdx.x;
    if (e < E) {
        atomicAdd(&g_deg_in[dst[e]], 1.0f);
        atomicAdd(&g_deg_out[src[e]], 1.0f);
    }
}

// ---------------- scan + fin ----------------
__global__ void scan_fin_kernel(int N, int E)
{
    __shared__ int warp_sums[32];
    __shared__ int warp_offs[32];
    __shared__ int chunk_tot;
    __shared__ int carry_s;
    const float* deg = (blockIdx.x == 0) ? g_deg_in : g_deg_out;
    int* off = (blockIdx.x == 0) ? g_off_in : g_off_out;
    int tid = threadIdx.x, lane = tid & 31, wid = tid >> 5;
    if (tid == 0) carry_s = 0;
    __syncthreads();
    for (int base = 0; base < N; base += 1024) {
        int i = base + tid;
        int v = (i < N) ? ((int)deg[i]) - 1 : 0;
        int incl = v;
        #pragma unroll
        for (int o = 1; o < 32; o <<= 1) {
            int t = __shfl_up_sync(0xffffffffu, incl, o);
            if (lane >= o) incl += t;
        }
        if (lane == 31) warp_sums[wid] = incl;
        __syncthreads();
        if (wid == 0) {
            int ws = warp_sums[lane];
            int wi = ws;
            #pragma unroll
            for (int o = 1; o < 32; o <<= 1) {
                int t = __shfl_up_sync(0xffffffffu, wi, o);
                if (lane >= o) wi += t;
            }
            warp_offs[lane] = wi - ws;
            if (lane == 31) chunk_tot = wi;
        }
        __syncthreads();
        if (i < N) off[i] = carry_s + warp_offs[wid] + incl - v;
        __syncthreads();
        if (tid == 0) carry_s += chunk_tot;
    }
    if (tid == 0) off[N] = E;
    if (blockIdx.x == 0) {
        for (int i = tid; i < N; i += 1024) {
            float a = g_deg_in[i];
            g_dinv_in[i] = rsqrtf(a);
            g_rdeg_in[i] = 1.0f / a;
            g_fill_in[i] = 0;
        }
    } else {
        for (int i = tid; i < N; i += 1024) {
            float a = g_deg_out[i];
            g_dinv_out[i] = rsqrtf(a);
            g_rdeg_out[i] = 1.0f / a;
            g_fill_out[i] = 0;
        }
    }
}

__global__ void fill_kernel(const int* __restrict__ src, const int* __restrict__ dst, int E)
{
    int e = blockIdx.x * blockDim.x + threadIdx.x;
    if (e < E) {
        int s = src[e], d = dst[e];
        int p = atomicAdd(&g_fill_in[d], 1);
        g_csr_in[g_off_in[d] + p] = s;
        int q = atomicAdd(&g_fill_out[s], 1);
        g_csr_out[g_off_out[s] + q] = d;
    }
}

// ---------------- per-layer dense part: mma.sync 2-term split, one direction per CTA ----------------
#define PH 136
#define PB 272
#define TILE_B (128 * PB)
#define OFF_W_HI 0
#define OFF_W_LO (1 * TILE_B)
#define OFF_A_HI (2 * TILE_B)
#define OFF_BIAS (3 * TILE_B)
#define OFF_ROOT (3 * TILE_B + 512)
#define SMEM_MMA (3 * TILE_B + 1024)

__global__ void __launch_bounds__(512, 2)
conv_mma_kernel(const float* __restrict__ Wf, const float* __restrict__ bf,
                const float* __restrict__ rootf,
                const float* __restrict__ Wr, const float* __restrict__ br,
                const float* __restrict__ rootr, int N)
{
    extern __shared__ __align__(16) char smc[];
    uint32_t sbase = smem_u32(smc);
    int tid = threadIdx.x;
    int dir = blockIdx.x & 1;

    const float* Wg = dir ? Wr : Wf;
    const float* bg = dir ? br : bf;
    const float* rg_g = dir ? rootr : rootf;

    float* sbias = (float*)(smc + OFF_BIAS);
    float* sroot = (float*)(smc + OFF_ROOT);
    if (tid < 128) { sbias[tid] = bg[tid]; sroot[tid] = rg_g[tid]; }

    for (int i = tid; i < 128 * 64; i += 512) {
        int c = i >> 6, k2 = (i & 63) << 1;
        int ho = c * PH + k2;
        float2 wv = *(const float2*)(Wg + c * 128 + k2);
        half2 hv = __float22half2_rn(wv);
        float2 bk = __half22float2(hv);
        *(half2*)((__half*)(smc + OFF_W_HI) + ho) = hv;
        *(half2*)((__half*)(smc + OFF_W_LO) + ho) =
            __float22half2_rn(make_float2(wv.x - bk.x, wv.y - bk.y));
    }
    __syncthreads();

    int w = tid >> 5, lane = tid & 31;
    int rg = w >> 1;
    int ch = w & 1;
    int wm = rg * 16;

    uint32_t aLaneOff = (uint32_t)((wm + (lane & 15)) * PB + ((lane >> 4) << 4));
    uint32_t bLaneOff = (uint32_t)(((((lane >> 4) << 3) + (lane & 7)) * PB) + ((((lane >> 3) & 1)) << 4));
    uint32_t aHiAddr = sbase + OFF_A_HI + aLaneOff;
    uint32_t bHiAddr = sbase + OFF_W_HI + (uint32_t)(ch * 64 * PB) + bLaneOff;
    uint32_t bLoAddr = sbase + OFF_W_LO + (uint32_t)(ch * 64 * PB) + bLaneOff;

    __half* xout = dir ? g_xr : g_xf;
    __half* aout = dir ? g_aggr : g_aggf;
    const float* rdegp = dir ? g_rdeg_out : g_rdeg_in;
    const float* dinvp = dir ? g_dinv_out : g_dinv_in;

    int numTiles = (N + 127) / 128;
    int step = gridDim.x >> 1;
    for (int tile = blockIdx.x >> 1; tile < numTiles; tile += step) {
        int base = tile * 128;
        __syncthreads();
        for (int i = tid; i < 128 * 16; i += 512) {
            int r = i >> 4, k8 = (i & 15) << 3;
            int row = base + r;
            uint4 v = make_uint4(0u, 0u, 0u, 0u);
            if (row < N) v = *(const uint4*)(g_h + (size_t)row * D + k8);
            *(uint4*)((__half*)(smc + OFF_A_HI) + r * PH + k8) = v;
        }
        __syncthreads();

        float acc[8][4];
        #pragma unroll
        for (int nf = 0; nf < 8; nf++)
            #pragma unroll
            for (int j = 0; j < 4; j++) acc[nf][j] = 0.f;

        #pragma unroll 1
        for (int kf = 0; kf < 8; kf++) {
            uint32_t ko = kf * 32;
            uint32_t ah[4];
            ldsm4(ah, aHiAddr + ko);
            #pragma unroll
            for (int nb = 0; nb < 4; nb++) {
                uint32_t boff = (uint32_t)(nb * 16 * PB) + ko;
                uint32_t bh[4], bl[4];
                ldsm4(bh, bHiAddr + boff);
                ldsm4(bl, bLoAddr + boff);
                mma16816(acc[nb * 2],     ah, bh[0], bh[1]);
                mma16816(acc[nb * 2],     ah, bl[0], bl[1]);
                mma16816(acc[nb * 2 + 1], ah, bh[2], bh[3]);
                mma16816(acc[nb * 2 + 1], ah, bl[2], bl[3]);
            }
        }

        int g = lane >> 2, t4 = lane & 3;
        int row0 = base + wm + g;
        int row1 = row0 + 8;
        float di0 = 0.f, rd0 = 0.f, di1 = 0.f, rd1 = 0.f;
        if (row0 < N) { di0 = dinvp[row0]; rd0 = rdegp[row0]; }
        if (row1 < N) { di1 = dinvp[row1]; rd1 = rdegp[row1]; }
        #pragma unroll
        for (int nf = 0; nf < 8; nf++) {
            int col = ch * 64 + nf * 8 + t4 * 2;
            float2 bb = *(const float2*)(sbias + col);
            float2 rr = *(const float2*)(sroot + col);
            if (row0 < N) {
                float v0 = acc[nf][0] + bb.x, v1 = acc[nf][1] + bb.y;
                *(half2*)(xout + (size_t)row0 * D + col) =
                    __floats2half2_rn(fmaxf(v0, 0.f) * di0, fmaxf(v1, 0.f) * di0);
                *(half2*)(aout + (size_t)row0 * D + col) =
                    __floats2half2_rn(fmaxf(v0 + rr.x, 0.f) * rd0, fmaxf(v1 + rr.y, 0.f) * rd0);
            }
            if (row1 < N) {
                float v2 = acc[nf][2] + bb.x, v3 = acc[nf][3] + bb.y;
                *(half2*)(xout + (size_t)row1 * D + col) =
                    __floats2half2_rn(fmaxf(v2, 0.f) * di1, fmaxf(v3, 0.f) * di1);
                *(half2*)(aout + (size_t)row1 * D + col) =
                    __floats2half2_rn(fmaxf(v2 + rr.x, 0.f) * rd1, fmaxf(v3 + rr.y, 0.f) * rd1);
            }
        }
    }
}

// ---------------- fused gather + LN + residual ----------------
__device__ __forceinline__ void gather_dir_2n(const int* __restrict__ csr, int s0, int s1,
                                              const __half* __restrict__ xs,
                                              int half, int l16, float* acc8)
{
    for (int j = s0; j < s1; j += 32) {
        int nn = s1 - j; if (nn > 32) nn = 32;
        int lane = half * 16 + l16;
        int idx = (lane < nn) ? csr[j + lane] : 0;
        if (nn == 32) {
            #pragma unroll
            for (int k = 0; k < 16; k++) {
                int id = __shfl_sync(0xffffffffu, idx, 2 * k + half);
                uint4 v = *(const uint4*)(xs + (size_t)id * D + l16 * 8);
                float2 f0 = __half22float2(*(half2*)&v.x);
                float2 f1 = __half22float2(*(half2*)&v.y);
                float2 f2 = __half22float2(*(half2*)&v.z);
                float2 f3 = __half22float2(*(half2*)&v.w);
                acc8[0] += f0.x; acc8[1] += f0.y; acc8[2] += f1.x; acc8[3] += f1.y;
                acc8[4] += f2.x; acc8[5] += f2.y; acc8[6] += f3.x; acc8[7] += f3.y;
            }
        } else {
            int pairs = (nn + 1) >> 1;
            for (int k = 0; k < pairs; k++) {
                int slot = 2 * k + half;
                int id = __shfl_sync(0xffffffffu, idx, slot < nn ? slot : 0);
                if (slot < nn) {
                    uint4 v = *(const uint4*)(xs + (size_t)id * D + l16 * 8);
                    float2 f0 = __half22float2(*(half2*)&v.x);
                    float2 f1 = __half22float2(*(half2*)&v.y);
                    float2 f2 = __half22float2(*(half2*)&v.z);
                    float2 f3 = __half22float2(*(half2*)&v.w);
                    acc8[0] += f0.x; acc8[1] += f0.y; acc8[2] += f1.x; acc8[3] += f1.y;
                    acc8[4] += f2.x; acc8[5] += f2.y; acc8[6] += f3.x; acc8[7] += f3.y;
                }
            }
        }
    }
}

__device__ __forceinline__ float4 combine_halves(const float* acc8, int half)
{
    float r[4];
    #pragma unroll
    for (int m = 0; m < 4; m++) {
        float send = half ? acc8[m] : acc8[4 + m];
        float recv = __shfl_xor_sync(0xffffffffu, send, 16);
        float keep = half ? acc8[4 + m] : acc8[m];
        r[m] = keep + recv;
    }
    return make_float4(r[0], r[1], r[2], r[3]);
}

__global__ void gather_post_kernel(const float* __restrict__ lng, const float* __restrict__ lnb,
                                   float* __restrict__ out, int NI, int N, int l)
{
    int gt = blockIdx.x * blockDim.x + threadIdx.x;
    int n = gt >> 5, lane = gt & 31;
    if (n >= N) return;
    int half = lane >> 4, l16 = lane & 15;
    int colb = l16 * 8 + half * 4;

    int si0 = g_off_in[n],  si1 = g_off_in[n + 1];
    int so0 = g_off_out[n], so1 = g_off_out[n + 1];
    float ci = g_dinv_in[n], co = g_dinv_out[n];

    float af8[8], ar8[8];
    #pragma unroll
    for (int j = 0; j < 8; j++) { af8[j] = 0.f; ar8[j] = 0.f; }

    gather_dir_2n(g_csr_in,  si0, si1, g_xf, half, l16, af8);
    gather_dir_2n(g_csr_out, so0, so1, g_xr, half, l16, ar8);

    float4 sf = combine_halves(af8, half);
    float4 sr = combine_halves(ar8, half);

    ull va = *(const ull*)(g_aggf + (size_t)n * D + colb);
    ull vr = *(const ull*)(g_aggr + (size_t)n * D + colb);
    float2 a01 = __half22float2(((half2*)&va)[0]);
    float2 a23 = __half22float2(((half2*)&va)[1]);
    float2 r01 = __half22float2(((half2*)&vr)[0]);
    float2 r23 = __half22float2(((half2*)&vr)[1]);

    float4 s;
    s.x = a01.x + sf.x * ci + r01.x + sr.x * co;
    s.y = a01.y + sf.y * ci + r01.y + sr.y * co;
    s.z = a23.x + sf.z * ci + r23.x + sr.z * co;
    s.w = a23.y + sf.w * ci + r23.y + sr.w * co;

    float sum = s.x + s.y + s.z + s.w;
    #pragma unroll
    for (int o = 16; o; o >>= 1) sum += __shfl_xor_sync(0xffffffffu, sum, o);
    float mu = sum * (1.0f / 128.0f);

    float dx = s.x - mu, dy = s.y - mu, dz = s.z - mu, dw = s.w - mu;
    float sq = dx * dx + dy * dy + dz * dz + dw * dw;
    #pragma unroll
    for (int o = 16; o; o >>= 1) sq += __shfl_xor_sync(0xffffffffu, sq, o);
    float rs = rsqrtf(sq * (1.0f / 128.0f) + 1e-5f);

    float4 gg = *(const float4*)(lng + colb);
    float4 bb = *(const float4*)(lnb + colb);
    float4 y;
    y.x = lrelu(dx * rs * gg.x + bb.x);
    y.y = lrelu(dy * rs * gg.y + bb.y);
    y.z = lrelu(dz * rs * gg.z + bb.z);
    y.w = lrelu(dw * rs * gg.w + bb.w);

    ull vh = *(const ull*)(g_h + (size_t)n * D + colb);
    float2 h01 = __half22float2(((half2*)&vh)[0]);
    float2 h23 = __half22float2(((half2*)&vh)[1]);
    float4 h;
    h.x = h01.x + y.x; h.y = h01.y + y.y; h.z = h23.x + y.z; h.w = h23.y + y.w;

    ull vo;
    ((half2*)&vo)[0] = __floats2half2_rn(h.x, h.y);
    ((half2*)&vo)[1] = __floats2half2_rn(h.z, h.w);
    *(ull*)(g_h + (size_t)n * D + colb) = vo;

    if (n >= NI) {
        *(float4*)(out + (size_t)(n - NI) * 512 + (size_t)(l + 1) * 128 + colb) = h;
    }
}

// ---------------- launch (fork-join streams: CSR chain overlaps enc + conv L0) ----------------
extern "C" void kernel_launch(void* const* d_in, const int* in_sizes, int n_in,
                              void* d_out, int out_size)
{
    const float* x      = (const float*)d_in[0];
    const float* xnet   = (const float*)d_in[1];
    const float* encW1  = (const float*)d_in[2];
    const float* encb1  = (const float*)d_in[3];
    const float* encW2  = (const float*)d_in[4];
    const float* encb2  = (const float*)d_in[5];
    const float* encnW1 = (const float*)d_in[6];
    const float* encnb1 = (const float*)d_in[7];
    const float* encnW2 = (const float*)d_in[8];
    const float* encnb2 = (const float*)d_in[9];
    const float* convW  = (const float*)d_in[10];
    const float* convb  = (const float*)d_in[11];
    const float* convr  = (const float*)d_in[12];
    const float* rconvW = (const float*)d_in[13];
    const float* rconvb = (const float*)d_in[14];
    const float* rconvr = (const float*)d_in[15];
    const float* lng    = (const float*)d_in[16];
    const float* lnb    = (const float*)d_in[17];
    const int*   src    = (const int*)d_in[18];
    const int*   dst    = (const int*)d_in[19];

    int NI = in_sizes[0] / 11;
    int NN = in_sizes[1] / 3;
    int N  = NI + NN;
    int E  = in_sizes[18];
    float* out = (float*)d_out;

    size_t sm1 = (size_t)(11 * 256 + 256 + 128 * 260 + 128 + 64 * 12 + 64 * 256) * 4;
    cudaFuncSetAttribute(enc_kernel, cudaFuncAttributeMaxDynamicSharedMemorySize, (int)sm1);
    cudaFuncSetAttribute(conv_mma_kernel, cudaFuncAttributeMaxDynamicSharedMemorySize, SMEM_MMA);

    cudaStream_t s;
    cudaStreamCreateWithFlags(&s, cudaStreamNonBlocking);
    cudaEvent_t evFork, evScan, evFill;
    cudaEventCreateWithFlags(&evFork, cudaEventDisableTiming);
    cudaEventCreateWithFlags(&evScan, cudaEventDisableTiming);
    cudaEventCreateWithFlags(&evFill, cudaEventDisableTiming);

    // fork: CSR chain on side stream
    cudaEventRecord(evFork, 0);
    cudaStreamWaitEvent(s, evFork, 0);
    deg_init_kernel<<<(N + 255) / 256, 256, 0, s>>>(N);
    deg_count_kernel<<<(E + 255) / 256, 256, 0, s>>>(src, dst, E);
    scan_fin_kernel<<<2, 1024, 0, s>>>(N, E);
    cudaEventRecord(evScan, s);
    fill_kernel<<<(E + 255) / 256, 256, 0, s>>>(src, dst, E);
    cudaEventRecord(evFill, s);

    // main stream: encoders, then per-layer pipeline
    enc_kernel<<<148, 512, sm1>>>(x, xnet, encW1, encb1, encW2, encb2,
                                  encnW1, encnb1, encnW2, encnb2, NI, NN, N, out);
    cudaStreamWaitEvent(0, evScan, 0);   // conv needs dinv/rdeg
    conv_mma_kernel<<<296, 512, SMEM_MMA>>>(convW, convb, convr, rconvW, rconvb, rconvr, N);
    cudaStreamWaitEvent(0, evFill, 0);   // gather needs CSR

    int node_threads = N * 32;
    gather_post_kernel<<<(node_threads + 255) / 256, 256>>>(lng, lnb, out, NI, N, 0);

    for (int l = 1; l < 3; l++) {
        conv_mma_kernel<<<296, 512, SMEM_MMA>>>(convW + (size_t)l * 16384, convb + l * 128, convr + l * 128,
                                                rconvW + (size_t)l * 16384, rconvb + l * 128, rconvr + l * 128, N);
        gather_post_kernel<<<(node_threads + 255) / 256, 256>>>(lng + l * 128, lnb + l * 128, out, NI, N, l);
    }
    // streams/events intentionally not destroyed: kernel_launch is called only a
    // handful of times (correctness + capture); no device memory is involved.
}